// round 15
// baseline (speedup 1.0000x reference)
#include <cuda_runtime.h>
#include <math.h>

#define NN 50000
#define NEE 800000

typedef unsigned long long ull;

// ---------------- scratch ----------------
__device__ float g_Q[NN*64];
__device__ float g_K[NN*64];
__device__ float g_V[NN*64];
__device__ float g_score[(size_t)NEE*64];   // edge-id ordered
__device__ float g_ex[NEE*8];               // exp(clamp(a)) per (edge, head)
__device__ float g_oV[NN*64];
__device__ float g_rowAcc[NN*64];
__device__ float g_nh1[NN*64];
__device__ float g_nh3[NN*64];
__device__ double g_sums[6*64];
__device__ float g_bnp[6*64];
// CSR by dst
__device__ int g_cnt[NN];
__device__ int g_base[NN];
__device__ int g_cursor[NN];
__device__ int g_eord[NEE];                 // CSR slot -> edge id
__device__ int g_esrc[NEE];                 // CSR slot -> src node
__device__ int g_bsum[256];

// ---------------- f32x2 helpers ----------------
__device__ __forceinline__ ull pk(float x, float y) {
    ull r; asm("mov.b64 %0,{%1,%2};" : "=l"(r) : "f"(x), "f"(y)); return r;
}
__device__ __forceinline__ void fma2(ull &d, ull a, ull b) {
    asm("fma.rn.f32x2 %0,%1,%2,%0;" : "+l"(d) : "l"(a), "l"(b));
}
__device__ __forceinline__ float2 upk(ull v) {
    float2 r; asm("mov.b64 {%0,%1},%2;" : "=f"(r.x), "=f"(r.y) : "l"(v)); return r;
}

// ---------------- K: init ----------------
__global__ void k_init() {
    int i = blockIdx.x*blockDim.x + threadIdx.x;
    if (i < NN) g_cnt[i] = 0;
    if (i < 6*64) g_sums[i] = 0.0;
}

// ---------------- CSR build ----------------
__global__ void k_hist(const int* __restrict__ eidx) {
    int e = blockIdx.x*blockDim.x + threadIdx.x;
    if (e < NEE) atomicAdd(&g_cnt[eidx[NEE + e]], 1);
}
__global__ void k_scan1() {
    __shared__ int sred[256];
    int t = threadIdx.x;
    int i = blockIdx.x*256 + t;
    int v = (i < NN) ? g_cnt[i] : 0;
    sred[t] = v; __syncthreads();
    for (int s = 128; s > 0; s >>= 1) { if (t < s) sred[t] += sred[t+s]; __syncthreads(); }
    if (t == 0) g_bsum[blockIdx.x] = sred[0];
}
__global__ void k_scan2() {
    __shared__ int s[256];
    int t = threadIdx.x;
    int v = (t < 196) ? g_bsum[t] : 0;
    s[t] = v; __syncthreads();
    for (int off = 1; off < 256; off <<= 1) {
        int x = (t >= off) ? s[t-off] : 0;
        __syncthreads(); s[t] += x; __syncthreads();
    }
    if (t < 196) g_bsum[t] = s[t] - v;
}
__global__ void k_scan3() {
    __shared__ int s[256];
    int t = threadIdx.x;
    int i = blockIdx.x*256 + t;
    int v = (i < NN) ? g_cnt[i] : 0;
    s[t] = v; __syncthreads();
    for (int off = 1; off < 256; off <<= 1) {
        int x = (t >= off) ? s[t-off] : 0;
        __syncthreads(); s[t] += x; __syncthreads();
    }
    int excl = s[t] - v + g_bsum[blockIdx.x];
    if (i < NN) { g_base[i] = excl; g_cursor[i] = excl; }
}
__global__ void k_sids(const int* __restrict__ eidx) {
    int e = blockIdx.x*blockDim.x + threadIdx.x;
    if (e < NEE) {
        int src = eidx[e];
        int pos = atomicAdd(&g_cursor[eidx[NEE + e]], 1);
        g_eord[pos] = e;
        g_esrc[pos] = src;
    }
}

// ---------------- K: Q,K,V = x @ W^T + b  (f32x2, resident weights) -------
__global__ void __launch_bounds__(256) k_qkv(const float* __restrict__ x,
    const float* __restrict__ Wq, const float* __restrict__ bq,
    const float* __restrict__ Wk, const float* __restrict__ bk,
    const float* __restrict__ Wv, const float* __restrict__ bv)
{
    extern __shared__ float dynq[];
    float* sW = dynq;           // 3 * 64*64, [m][d*64 + j]
    float* sX = dynq + 12288;   // 128*64, [n][d ^ swz(n)]
    int t = threadIdx.x;
    int eg = t >> 4, cg = t & 15;
    int j0 = cg*4;
    int eswz = (eg & 7) << 2;
    const float* Ws[3] = {Wq, Wk, Wv};
    const float* bs[3] = {bq, bk, bv};
    float* outs[3] = {g_Q, g_K, g_V};

    #pragma unroll
    for (int m = 0; m < 3; m++)
        for (int idx = t; idx < 4096; idx += 256) {
            int j = idx >> 6, d = idx & 63;
            sW[m*4096 + d*64 + j] = Ws[m][j*64 + d];
        }
    ull biasm[3][2];
    #pragma unroll
    for (int m = 0; m < 3; m++) {
        float4 b = *(const float4*)&bs[m][j0];
        biasm[m][0] = pk(b.x, b.y); biasm[m][1] = pk(b.z, b.w);
    }
    __syncthreads();

    int ntiles = (NN + 127) / 128;   // 391
    for (int g = blockIdx.x; g < ntiles; g += gridDim.x) {
        int n0 = g*128;
        __syncthreads();
        #pragma unroll
        for (int k = 0; k < 8; k++) {
            int lin = t + k*256;
            int e = lin >> 4, d0 = (lin & 15)*4;
            int n = n0 + e;
            float4 v = (n < NN) ? *(const float4*)&x[(size_t)n*64 + d0]
                                : make_float4(0.f,0.f,0.f,0.f);
            int ds = d0 ^ (((e >> 3) & 7) << 2);
            *(float4*)&sX[e*64 + ds] = v;
        }
        __syncthreads();
        int abase = eg*8*64;
        #pragma unroll
        for (int m = 0; m < 3; m++) {
            ull acc[8][2];
            #pragma unroll
            for (int e = 0; e < 8; e++) { acc[e][0] = biasm[m][0]; acc[e][1] = biasm[m][1]; }
            const float* W = &sW[m*4096];
            #pragma unroll 4
            for (int d2 = 0; d2 < 64; d2 += 2) {
                int dx = d2 ^ eswz;
                float2 a2[8];
                #pragma unroll
                for (int i = 0; i < 8; i++) a2[i] = *(const float2*)&sX[abase + i*64 + dx];
                float4 w0 = *(const float4*)&W[d2*64 + j0];
                float4 w1 = *(const float4*)&W[(d2+1)*64 + j0];
                ull wp00 = pk(w0.x,w0.y), wp01 = pk(w0.z,w0.w);
                ull wp10 = pk(w1.x,w1.y), wp11 = pk(w1.z,w1.w);
                #pragma unroll
                for (int e = 0; e < 8; e++) {
                    ull ae0 = pk(a2[e].x, a2[e].x);
                    ull ae1 = pk(a2[e].y, a2[e].y);
                    fma2(acc[e][0], ae0, wp00); fma2(acc[e][1], ae0, wp01);
                    fma2(acc[e][0], ae1, wp10); fma2(acc[e][1], ae1, wp11);
                }
            }
            float* o = outs[m];
            #pragma unroll
            for (int e = 0; e < 8; e++) {
                int n = n0 + eg*8 + e;
                if (n < NN) {
                    float2 r0 = upk(acc[e][0]), r1 = upk(acc[e][1]);
                    *(float4*)&o[(size_t)n*64 + j0] = make_float4(r0.x, r0.y, r1.x, r1.y);
                }
            }
        }
    }
}

// ---------------- K: fused edge pipeline (64-edge tile, in-place buffer) ----
// smem: weights 48KB + one 16KB tile buffer (ea -> score in place) = 64KB -> 3 CTAs/SM.
__global__ void __launch_bounds__(256, 3) k_edge(
    const float* __restrict__ ea, const int* __restrict__ eidx,
    const float* __restrict__ We, const float* __restrict__ be,
    const float* __restrict__ Aw,
    const float* __restrict__ Eo_w, const float* __restrict__ Eo_b,
    float* __restrict__ out_eh)
{
    extern __shared__ float dyn[];
    float* sWa = dyn;            // [d][p]  E1 cols permuted: colA(p) = (p>>3)*16 + (p&7)
    float* sWb = dyn + 4096;     // [d][p]  E2 cols (colA+8)
    float* sEo = dyn + 8192;     // [k][j]
    float* sB  = dyn + 12288;    // 64x64 tile: ea (phase1) then score (phase2), swizzled

    int t = threadIdx.x;
    int eg = t >> 4;             // 0..15 -> 4 edges each
    int cg = t & 15;             // 0..15
    int h  = cg >> 1, q = cg & 1;
    int j1  = h*16 + q*4;        // E1 col base; E2 at +8
    int sc0 = h*8 + q*4;         // score col base (phase1)
    int j0  = cg*4;              // eh col base (phase2)
    int eswz = ((eg >> 1) & 7) << 2;   // row group of this thread's 4 edges

    for (int idx = t; idx < 4096; idx += 256) {
        int d = idx & 63, p = idx >> 6;
        int colA = ((p >> 3) << 4) + (p & 7);
        sWa[d*64 + p] = We[colA*64 + d];
        sWb[d*64 + p] = We[(colA + 8)*64 + d];
        int j = idx >> 6, k = idx & 63;
        sEo[k*64 + j] = Eo_w[j*64 + k];
    }
    float4 bA = *(const float4*)&be[j1];
    float4 bB = *(const float4*)&be[j1 + 8];
    ull biasp[4] = { pk(bA.x,bA.y), pk(bA.z,bA.w), pk(bB.x,bB.y), pk(bB.z,bB.w) };
    float aw0 = Aw[(q*4+0)*8 + h], aw1 = Aw[(q*4+1)*8 + h];
    float aw2 = Aw[(q*4+2)*8 + h], aw3 = Aw[(q*4+3)*8 + h];
    float4 b2 = *(const float4*)&Eo_b[j0];
    ull bias2p[2] = { pk(b2.x,b2.y), pk(b2.z,b2.w) };

    float cs[4] = {0,0,0,0}, cq[4] = {0,0,0,0};
    int abase = eg*4*64;

    for (int g = blockIdx.x; g < NEE/64; g += gridDim.x) {
        int e0 = g*64;
        __syncthreads();   // previous tile's phase-2 reads done before reload
        #pragma unroll
        for (int k = 0; k < 4; k++) {
            int lin = t + k*256;
            int e = lin >> 4, d0 = (lin & 15)*4;
            float4 v = *(const float4*)&ea[(size_t)(e0+e)*64 + d0];
            int ds = d0 ^ (((e >> 3) & 7) << 2);
            *(float4*)&sB[e*64 + ds] = v;
        }
        __syncthreads();

        // ---- phase 1 GEMM: E = ea @ We^T (4 edges x 8 cols) ----
        ull acc[4][4];
        #pragma unroll
        for (int e = 0; e < 4; e++) {
            acc[e][0]=biasp[0]; acc[e][1]=biasp[1]; acc[e][2]=biasp[2]; acc[e][3]=biasp[3];
        }
        #pragma unroll 4
        for (int d2 = 0; d2 < 64; d2 += 2) {
            int dx = d2 ^ eswz;
            float2 a2[4];
            #pragma unroll
            for (int i = 0; i < 4; i++) a2[i] = *(const float2*)&sB[abase + i*64 + dx];
            float4 wA0 = *(const float4*)&sWa[d2*64 + cg*4];
            float4 wB0 = *(const float4*)&sWb[d2*64 + cg*4];
            float4 wA1 = *(const float4*)&sWa[(d2+1)*64 + cg*4];
            float4 wB1 = *(const float4*)&sWb[(d2+1)*64 + cg*4];
            ull wa00 = pk(wA0.x,wA0.y), wa01 = pk(wA0.z,wA0.w);
            ull wb00 = pk(wB0.x,wB0.y), wb01 = pk(wB0.z,wB0.w);
            ull wa10 = pk(wA1.x,wA1.y), wa11 = pk(wA1.z,wA1.w);
            ull wb10 = pk(wB1.x,wB1.y), wb11 = pk(wB1.z,wB1.w);
            #pragma unroll
            for (int e = 0; e < 4; e++) {
                ull ae0 = pk(a2[e].x, a2[e].x);
                fma2(acc[e][0], ae0, wa00); fma2(acc[e][1], ae0, wa01);
                fma2(acc[e][2], ae0, wb00); fma2(acc[e][3], ae0, wb01);
                ull ae1 = pk(a2[e].y, a2[e].y);
                fma2(acc[e][0], ae1, wa10); fma2(acc[e][1], ae1, wa11);
                fma2(acc[e][2], ae1, wb10); fma2(acc[e][3], ae1, wb11);
            }
        }
        __syncthreads();   // all ea reads complete before in-place overwrite

        // ---- epilogue 1: score -> gmem + sB (in place), exp(clamp(a)) -> g_ex
        #pragma unroll
        for (int e = 0; e < 4; e++) {
            int le = eg*4 + e;
            int E = e0 + le;
            int src = eidx[E], dst = eidx[NEE + E];
            float2 A0 = upk(acc[e][0]), A1 = upk(acc[e][1]);
            float2 B0 = upk(acc[e][2]), B1 = upk(acc[e][3]);
            float s20 = A0.x*B0.x, s21 = A0.y*B0.y, s22 = A1.x*B1.x, s23 = A1.y*B1.y;
            float ss0 = copysignf(sqrtf(fabsf(s20)), s20);
            float ss1 = copysignf(sqrtf(fabsf(s21)), s21);
            float ss2 = copysignf(sqrtf(fabsf(s22)), s22);
            float ss3 = copysignf(sqrtf(fabsf(s23)), s23);
            float4 Kv = *(const float4*)&g_K[(size_t)src*64 + sc0];
            float4 Qv = *(const float4*)&g_Q[(size_t)dst*64 + sc0];
            float c0 = fmaxf(Kv.x + Qv.x + ss0, 0.f);
            float c1 = fmaxf(Kv.y + Qv.y + ss1, 0.f);
            float c2 = fmaxf(Kv.z + Qv.z + ss2, 0.f);
            float c3 = fmaxf(Kv.w + Qv.w + ss3, 0.f);
            float4 cv = make_float4(c0,c1,c2,c3);
            *(float4*)&g_score[(size_t)E*64 + sc0] = cv;
            *(float4*)&sB[le*64 + (sc0 ^ eswz)] = cv;
            float av = c0*aw0 + c1*aw1 + c2*aw2 + c3*aw3;
            av += __shfl_xor_sync(0xffffffffu, av, 1);
            if (q == 0) {
                av = fminf(fmaxf(av, -5.f), 5.f);
                g_ex[(size_t)E*8 + h] = expf(av);   // a in [-5,5]: exp safe, max-pass redundant
            }
        }
        __syncthreads();   // score tile complete

        // ---- phase 2 GEMM: eh = ea + score @ Eo^T (4 edges x 4 cols) ----
        ull acc2[4][2];
        #pragma unroll
        for (int e = 0; e < 4; e++) { acc2[e][0] = bias2p[0]; acc2[e][1] = bias2p[1]; }
        #pragma unroll 4
        for (int d2 = 0; d2 < 64; d2 += 2) {
            int dx = d2 ^ eswz;
            float2 a2[4];
            #pragma unroll
            for (int i = 0; i < 4; i++) a2[i] = *(const float2*)&sB[abase + i*64 + dx];
            float4 w0 = *(const float4*)&sEo[d2*64 + j0];
            float4 w1 = *(const float4*)&sEo[(d2+1)*64 + j0];
            ull wp00 = pk(w0.x,w0.y), wp01 = pk(w0.z,w0.w);
            ull wp10 = pk(w1.x,w1.y), wp11 = pk(w1.z,w1.w);
            #pragma unroll
            for (int e = 0; e < 4; e++) {
                ull ae0 = pk(a2[e].x, a2[e].x);
                ull ae1 = pk(a2[e].y, a2[e].y);
                fma2(acc2[e][0], ae0, wp00); fma2(acc2[e][1], ae0, wp01);
                fma2(acc2[e][0], ae1, wp10); fma2(acc2[e][1], ae1, wp11);
            }
        }
        // ---- epilogue 2: residual re-read from gmem, store eh, BN sums ----
        #pragma unroll
        for (int e = 0; e < 4; e++) {
            int le = eg*4 + e;
            size_t E = (size_t)(e0 + le);
            float2 r0 = upk(acc2[e][0]), r1 = upk(acc2[e][1]);
            float4 q0 = *(const float4*)&ea[E*64 + j0];
            float o0 = r0.x + q0.x, o1 = r0.y + q0.y;
            float o2 = r1.x + q0.z, o3 = r1.y + q0.w;
            *(float4*)&out_eh[E*64 + j0] = make_float4(o0,o1,o2,o3);
            cs[0]+=o0; cs[1]+=o1; cs[2]+=o2; cs[3]+=o3;
            cq[0]+=o0*o0; cq[1]+=o1*o1; cq[2]+=o2*o2; cq[3]+=o3*o3;
        }
    }
    // BN sums reduce
    __syncthreads();
    float* red = sB;
    if (t < 128) red[t] = 0.f;
    __syncthreads();
    #pragma unroll
    for (int i = 0; i < 4; i++) {
        atomicAdd(&red[j0 + i], cs[i]);
        atomicAdd(&red[64 + j0 + i], cq[i]);
    }
    __syncthreads();
    if (t < 64) {
        atomicAdd(&g_sums[t],      (double)red[t]);
        atomicAdd(&g_sums[64 + t], (double)red[64 + t]);
    }
}

// ---------------- K: per-node attention accumulate (single pass) -----------
__global__ void __launch_bounds__(256) k_nattn() {
    int warp = threadIdx.x >> 5, lane = threadIdx.x & 31;
    int n = blockIdx.x*8 + warp;
    int c2 = lane*2;
    int deg = g_cnt[n];
    int base = g_base[n];
    if (deg == 0) {
        *(float2*)&g_oV[(size_t)n*64 + c2]     = make_float2(0.f, 0.f);
        *(float2*)&g_rowAcc[(size_t)n*64 + c2] = make_float2(0.f, 0.f);
        return;
    }
    int hh = lane >> 2;   // head owning cols c2, c2+1
    float dnacc = 0.f;
    float av0=0.f, av1=0.f, ar0=0.f, ar1=0.f;
    #pragma unroll 2
    for (int k = 0; k < deg; k++) {
        int idx = base + k;
        int eid = g_eord[idx];
        int src = g_esrc[idx];
        float ex = g_ex[(size_t)eid*8 + hh];
        dnacc += ex;
        float2 v = *(const float2*)&g_V[(size_t)src*64 + c2];
        float2 s = *(const float2*)&g_score[(size_t)eid*64 + c2];
        av0 = fmaf(v.x, ex, av0); av1 = fmaf(v.y, ex, av1);
        ar0 = fmaf(s.x, ex, ar0); ar1 = fmaf(s.y, ex, ar1);
    }
    float myr = 1.f / (dnacc + 1e-16f);
    *(float2*)&g_oV[(size_t)n*64 + c2]     = make_float2(av0*myr, av1*myr);
    *(float2*)&g_rowAcc[(size_t)n*64 + c2] = make_float2(ar0*myr, ar1*myr);
}

// ---------------- K: rowV einsum + deg + No gemm + residual + BN1 sums ----
__global__ void __launch_bounds__(256) k_node1(
    const float* __restrict__ x, const float* __restrict__ log_deg,
    const float* __restrict__ VeRow, const float* __restrict__ deg_coef,
    const float* __restrict__ No_w, const float* __restrict__ No_b)
{
    __shared__ __align__(16) float sNoT[64*64];
    __shared__ float sVe[512];
    __shared__ float sDC0[64], sDC1[64], sNob[64];
    __shared__ __align__(16) float sNH[16][64];
    __shared__ __align__(16) float sRA[16][64];
    int t = threadIdx.x;
    for (int i = t; i < 64*64; i += 256)
        sNoT[(i&63)*64 + (i>>6)] = No_w[i];
    for (int i = t; i < 512; i += 256) sVe[i] = VeRow[i];
    if (t < 64) { sDC0[t]=deg_coef[t*2]; sDC1[t]=deg_coef[t*2+1]; sNob[t]=No_b[t]; }
    __syncthreads();

    float cs0=0,cs1=0,cs2=0,cs3=0, cq0=0,cq1=0,cq2=0,cq3=0;
    int ngroups = NN/16;
    for (int g = blockIdx.x; g < ngroups; g += gridDim.x) {
        int n0 = g*16;
        for (int i = t; i < 16*64; i += 256)
            sRA[i>>6][i&63] = g_rowAcc[(size_t)(n0 + (i>>6))*64 + (i&63)];
        __syncthreads();
        int j = t & 63, h = j >> 3;
        #pragma unroll
        for (int qq = 0; qq < 4; qq++) {
            int le = (t >> 6) + qq*4;
            int n = n0 + le;
            float rv = 0.f;
            #pragma unroll
            for (int d = 0; d < 8; d++)
                rv = fmaf(sRA[le][h*8+d], sVe[d*64 + j], rv);
            float nh0 = g_oV[(size_t)n*64 + j] + rv;
            float ld = log_deg[n];
            sNH[le][j] = nh0 * (sDC0[j] + ld*sDC1[j]);
        }
        __syncthreads();
        {
            int j4 = (t & 15) * 4;
            int le = t >> 4;
            int n = n0 + le;
            float4 acc = make_float4(sNob[j4], sNob[j4+1], sNob[j4+2], sNob[j4+3]);
            #pragma unroll 8
            for (int d = 0; d < 64; d++) {
                float a = sNH[le][d];
                float4 w = *(const float4*)&sNoT[d*64 + j4];
                acc.x = fmaf(a,w.x,acc.x); acc.y = fmaf(a,w.y,acc.y);
                acc.z = fmaf(a,w.z,acc.z); acc.w = fmaf(a,w.w,acc.w);
            }
            float4 xr = *(const float4*)&x[(size_t)n*64 + j4];
            acc.x += xr.x; acc.y += xr.y; acc.z += xr.z; acc.w += xr.w;
            *(float4*)&g_nh1[(size_t)n*64 + j4] = acc;
            cs0 += acc.x; cs1 += acc.y; cs2 += acc.z; cs3 += acc.w;
            cq0 += acc.x*acc.x; cq1 += acc.y*acc.y; cq2 += acc.z*acc.z; cq3 += acc.w*acc.w;
        }
        __syncthreads();
    }
    float* red = &sRA[0][0];
    if (t < 128) red[t] = 0.f;
    __syncthreads();
    int j4 = (t & 15) * 4;
    atomicAdd(&red[j4+0], cs0); atomicAdd(&red[j4+1], cs1);
    atomicAdd(&red[j4+2], cs2); atomicAdd(&red[j4+3], cs3);
    atomicAdd(&red[64+j4+0], cq0); atomicAdd(&red[64+j4+1], cq1);
    atomicAdd(&red[64+j4+2], cq2); atomicAdd(&red[64+j4+3], cq3);
    __syncthreads();
    if (t < 64) {
        atomicAdd(&g_sums[128+t], (double)red[t]);
        atomicAdd(&g_sums[192+t], (double)red[64+t]);
    }
}

// ---------------- K: BN params (edge, node1) ----------------
__global__ void k_bnp1(const float* __restrict__ g1e, const float* __restrict__ b1e,
                       const float* __restrict__ g1n, const float* __restrict__ b1n) {
    int t = threadIdx.x;
    if (t < 64) {
        double mu = g_sums[t] / (double)NEE;
        double var = g_sums[64+t] / (double)NEE - mu*mu;
        float sc = (float)(1.0/sqrt(var + 1e-5)) * g1e[t];
        g_bnp[t] = sc; g_bnp[64+t] = b1e[t] - (float)mu*sc;
    } else {
        int j = t - 64;
        double mu = g_sums[128+j] / (double)NN;
        double var = g_sums[192+j] / (double)NN - mu*mu;
        float sc = (float)(1.0/sqrt(var + 1e-5)) * g1n[j];
        g_bnp[128+j] = sc; g_bnp[192+j] = b1n[j] - (float)mu*sc;
    }
}

// ---------------- K: BN1 apply + MLP + residual + BN2 sums ----------------
__global__ void __launch_bounds__(256) k_mlp(
    const float* __restrict__ W1, const float* __restrict__ b1f,
    const float* __restrict__ W2, const float* __restrict__ b2f)
{
    extern __shared__ float dynm[];
    float* sW1 = dynm;           // [d][k] 64*128
    float* sW2 = dynm + 8192;    // [k][j] 128*64
    float* sHf = dynm + 16384;   // [le][k] 16*128
    float* sBv = dynm + 18432;   // [le][j] 16*64
    __shared__ float sb1[128];
    __shared__ float sb2[64], sScale[64], sShift[64];
    int t = threadIdx.x;
    if (t < 128) sb1[t] = b1f[t];
    if (t < 64) { sb2[t]=b2f[t]; sScale[t]=g_bnp[128+t]; sShift[t]=g_bnp[192+t]; }
    for (int i = t; i < 128*64; i += 256) {
        int k = i >> 6, d = i & 63;
        sW1[d*128 + k] = W1[i];               // W1[k,d] -> [d][k]
        int j = i >> 7, k2 = i & 127;
        sW2[k2*64 + j] = W2[i];               // W2[j,k] -> [k][j]
    }

    float cs0=0,cs1=0,cs2=0,cs3=0, cq0=0,cq1=0,cq2=0,cq3=0;
    int ngroups = NN/16;
    for (int g = blockIdx.x; g < ngroups; g += gridDim.x) {
        int n0 = g*16;
        __syncthreads();
        for (int i = t; i < 16*64; i += 256) {
            int le = i >> 6, j = i & 63;
            sBv[le*64 + j] = g_nh1[(size_t)(n0+le)*64 + j]*sScale[j] + sShift[j];
        }
        __syncthreads();
        {   // h = relu(bnv @ W1^T + b1)
            int k4 = (t & 31) * 4;
            int le0 = t >> 5;
            float4 acc0 = make_float4(sb1[k4], sb1[k4+1], sb1[k4+2], sb1[k4+3]);
            float4 acc1 = acc0;
            #pragma unroll 8
            for (int d = 0; d < 64; d++) {
                float4 w = *(const float4*)&sW1[d*128 + k4];
                float a0 = sBv[le0*64 + d], a1 = sBv[(le0+8)*64 + d];
                acc0.x = fmaf(a0,w.x,acc0.x); acc0.y = fmaf(a0,w.y,acc0.y);
                acc0.z = fmaf(a0,w.z,acc0.z); acc0.w = fmaf(a0,w.w,acc0.w);
                acc1.x = fmaf(a1,w.x,acc1.x); acc1.y = fmaf(a1,w.y,acc1.y);
                acc1.z = fmaf(a1,w.z,acc1.z); acc1.w = fmaf(a1,w.w,acc1.w);
            }
            acc0.x=fmaxf(acc0.x,0.f); acc0.y=fmaxf(acc0.y,0.f); acc0.z=fmaxf(acc0.z,0.f); acc0.w=fmaxf(acc0.w,0.f);
            acc1.x=fmaxf(acc1.x,0.f); acc1.y=fmaxf(acc1.y,0.f); acc1.z=fmaxf(acc1.z,0.f); acc1.w=fmaxf(acc1.w,0.f);
            *(float4*)&sHf[le0*128 + k4]     = acc0;
            *(float4*)&sHf[(le0+8)*128 + k4] = acc1;
        }
        __syncthreads();
        {   // nh3 = bnv + h @ W2^T + b2
            int j4 = (t & 15) * 4;
            int le = t >> 4;
            int n = n0 + le;
            float4 acc = make_float4(sb2[j4], sb2[j4+1], sb2[j4+2], sb2[j4+3]);
            #pragma unroll 8
            for (int k = 0; k < 128; k++) {
                float a = sHf[le*128 + k];
                float4 w = *(const float4*)&sW2[k*64 + j4];
                acc.x = fmaf(a,w.x,acc.x); acc.y = fmaf(a,w.y,acc.y);
                acc.z = fmaf(a,w.z,acc.z); acc.w = fmaf(a,w.w,acc.w);
            }
            acc.x += sBv[le*64 + j4+0]; acc.y += sBv[le*64 + j4+1];
            acc.z += sBv[le*64 + j4+2]; acc.w += sBv[le*64 + j4+3];
            *(float4*)&g_nh3[(size_t)n*64 + j4] = acc;
            cs0 += acc.x; cs1 += acc.y; cs2 += acc.z; cs3 += acc.w;
            cq0 += acc.x*acc.x; cq1 += acc.y*acc.y; cq2 += acc.z*acc.z; cq3 += acc.w*acc.w;
        }
    }
    __syncthreads();
    float* red = sHf;
    if (t < 128) red[t] = 0.f;
    __syncthreads();
    int j4 = (t & 15) * 4;
    atomicAdd(&red[j4+0], cs0); atomicAdd(&red[j4+1], cs1);
    atomicAdd(&red[j4+2], cs2); atomicAdd(&red[j4+3], cs3);
    atomicAdd(&red[64+j4+0], cq0); atomicAdd(&red[64+j4+1], cq1);
    atomicAdd(&red[64+j4+2], cq2); atomicAdd(&red[64+j4+3], cq3);
    __syncthreads();
    if (t < 64) {
        atomicAdd(&g_sums[256+t], (double)red[t]);
        atomicAdd(&g_sums[320+t], (double)red[64+t]);
    }
}

// ---------------- K: BN2 params ----------------
__global__ void k_bnp2(const float* __restrict__ g2, const float* __restrict__ beta2) {
    int t = threadIdx.x;
    double mu = g_sums[256+t] / (double)NN;
    double var = g_sums[320+t] / (double)NN - mu*mu;
    float sc = (float)(1.0/sqrt(var + 1e-5)) * g2[t];
    g_bnp[256+t] = sc; g_bnp[320+t] = beta2[t] - (float)mu*sc;
}

// ---------------- K: apply BN2 (nodes) + edge BN (in place) ----------------
__global__ void k_finish(float* __restrict__ out) {
    const int NODE4 = NN*16;
    const int TOT4 = NODE4 + NEE*16;
    int q = blockIdx.x*blockDim.x + threadIdx.x;
    if (q >= TOT4) return;
    int j = (q*4) & 63;
    if (q < NODE4) {
        float4 v = *(const float4*)&g_nh3[(size_t)q*4];
        float4 sc = *(const float4*)&g_bnp[256+j];
        float4 sh = *(const float4*)&g_bnp[320+j];
        float4 r;
        r.x = v.x*sc.x + sh.x; r.y = v.y*sc.y + sh.y;
        r.z = v.z*sc.z + sh.z; r.w = v.w*sc.w + sh.w;
        ((float4*)out)[q] = r;
    } else {
        float4 v = ((const float4*)out)[q];
        float4 sc = *(const float4*)&g_bnp[j];
        float4 sh = *(const float4*)&g_bnp[64+j];
        float4 r;
        r.x = v.x*sc.x + sh.x; r.y = v.y*sc.y + sh.y;
        r.z = v.z*sc.z + sh.z; r.w = v.w*sc.w + sh.w;
        ((float4*)out)[q] = r;
    }
}

// ---------------- launch ----------------
extern "C" void kernel_launch(void* const* d_in, const int* in_sizes, int n_in,
                              void* d_out, int out_size) {
    const float* x        = (const float*)d_in[0];
    const float* ea       = (const float*)d_in[1];
    const float* log_deg  = (const float*)d_in[2];
    const int*   eidx     = (const int*)d_in[3];
    const float* Wq = (const float*)d_in[4];  const float* bq = (const float*)d_in[5];
    const float* Wk = (const float*)d_in[6];  const float* bk = (const float*)d_in[7];
    const float* Wv = (const float*)d_in[8];  const float* bv = (const float*)d_in[9];
    const float* We = (const float*)d_in[10]; const float* be = (const float*)d_in[11];
    const float* Aw = (const float*)d_in[12]; const float* VeRow = (const float*)d_in[13];
    const float* deg_coef = (const float*)d_in[14];
    const float* No_w = (const float*)d_in[15]; const float* No_b = (const float*)d_in[16];
    const float* Eo_w = (const float*)d_in[17]; const float* Eo_b = (const float*)d_in[18];
    const float* W1 = (const float*)d_in[19]; const float* b1f = (const float*)d_in[20];
    const float* W2 = (const float*)d_in[21]; const float* b2f = (const float*)d_in[22];
    const float* g1n = (const float*)d_in[23]; const float* b1n = (const float*)d_in[24];
    const float* g1e = (const float*)d_in[25]; const float* b1e = (const float*)d_in[26];
    const float* g2  = (const float*)d_in[27]; const float* beta2 = (const float*)d_in[28];

    float* out = (float*)d_out;
    float* out_eh = out + (size_t)NN*64;

    const int QKV_SMEM  = (12288 + 8192) * 4;   // 80 KB
    const int EDGE_SMEM = 16384 * 4;            // 64 KB -> 3 CTAs/SM
    const int MLP_SMEM  = 19456 * 4;            // 76 KB
    cudaFuncSetAttribute(k_qkv,  cudaFuncAttributeMaxDynamicSharedMemorySize, QKV_SMEM);
    cudaFuncSetAttribute(k_edge, cudaFuncAttributeMaxDynamicSharedMemorySize, EDGE_SMEM);
    cudaFuncSetAttribute(k_mlp,  cudaFuncAttributeMaxDynamicSharedMemorySize, MLP_SMEM);

    // order: k_edge at launch index 3 so ncu's fixed capture lands on it
    k_qkv   <<<391, 256, QKV_SMEM>>>(x, Wq, bq, Wk, bk, Wv, bv);     // 0
    k_init  <<<196, 256>>>();                                        // 1
    k_hist  <<<3125, 256>>>(eidx);                                   // 2
    k_edge  <<<4440, 256, EDGE_SMEM>>>(ea, eidx, We, be, Aw, Eo_w, Eo_b, out_eh); // 3
    k_scan1 <<<196, 256>>>();                                        // 4
    k_scan2 <<<1, 256>>>();                                          // 5
    k_scan3 <<<196, 256>>>();                                        // 6
    k_sids  <<<3125, 256>>>(eidx);                                   // 7
    k_nattn <<<6250, 256>>>();                                       // 8
    k_node1 <<<592, 256>>>(x, log_deg, VeRow, deg_coef, No_w, No_b); // 9
    k_bnp1  <<<1, 128>>>(g1e, b1e, g1n, b1n);                        // 10
    k_mlp   <<<592, 256, MLP_SMEM>>>(W1, b1f, W2, b2f);              // 11
    k_bnp2  <<<1, 64>>>(g2, beta2);                                  // 12
    k_finish<<<53125, 256>>>(out);                                   // 13
}

// round 16
// speedup vs baseline: 1.0034x; 1.0034x over previous
#include <cuda_runtime.h>
#include <math.h>

#define NN 50000
#define NEE 800000

typedef unsigned long long ull;

// ---------------- scratch ----------------
__device__ float g_Q[NN*64];
__device__ float g_K[NN*64];
__device__ float g_V[NN*64];
__device__ float g_score[(size_t)NEE*64];   // edge-id ordered
__device__ float g_ex[NEE*8];               // exp(clamp(a)) per (edge, head)
__device__ float g_oV[NN*64];
__device__ float g_rowAcc[NN*64];
__device__ float g_nh1[NN*64];
__device__ float g_nh3[NN*64];
__device__ double g_sums[6*64];
__device__ float g_bnp[6*64];
// CSR by dst
__device__ int g_cnt[NN];
__device__ int g_base[NN];
__device__ int g_cursor[NN];
__device__ int g_eord[NEE];                 // CSR slot -> edge id
__device__ int g_esrc[NEE];                 // CSR slot -> src node
__device__ int g_bsum[256];

// ---------------- f32x2 helpers ----------------
__device__ __forceinline__ ull pk(float x, float y) {
    ull r; asm("mov.b64 %0,{%1,%2};" : "=l"(r) : "f"(x), "f"(y)); return r;
}
__device__ __forceinline__ void fma2(ull &d, ull a, ull b) {
    asm("fma.rn.f32x2 %0,%1,%2,%0;" : "+l"(d) : "l"(a), "l"(b));
}
__device__ __forceinline__ float2 upk(ull v) {
    float2 r; asm("mov.b64 {%0,%1},%2;" : "=f"(r.x), "=f"(r.y) : "l"(v)); return r;
}

// ---------------- K: init ----------------
__global__ void k_init() {
    int i = blockIdx.x*blockDim.x + threadIdx.x;
    if (i < NN) g_cnt[i] = 0;
    if (i < 6*64) g_sums[i] = 0.0;
}

// ---------------- CSR build ----------------
__global__ void k_hist(const int* __restrict__ eidx) {
    int e = blockIdx.x*blockDim.x + threadIdx.x;
    if (e < NEE) atomicAdd(&g_cnt[eidx[NEE + e]], 1);
}
__global__ void k_scan1() {
    __shared__ int sred[256];
    int t = threadIdx.x;
    int i = blockIdx.x*256 + t;
    int v = (i < NN) ? g_cnt[i] : 0;
    sred[t] = v; __syncthreads();
    for (int s = 128; s > 0; s >>= 1) { if (t < s) sred[t] += sred[t+s]; __syncthreads(); }
    if (t == 0) g_bsum[blockIdx.x] = sred[0];
}
__global__ void k_scan2() {
    __shared__ int s[256];
    int t = threadIdx.x;
    int v = (t < 196) ? g_bsum[t] : 0;
    s[t] = v; __syncthreads();
    for (int off = 1; off < 256; off <<= 1) {
        int x = (t >= off) ? s[t-off] : 0;
        __syncthreads(); s[t] += x; __syncthreads();
    }
    if (t < 196) g_bsum[t] = s[t] - v;
}
__global__ void k_scan3() {
    __shared__ int s[256];
    int t = threadIdx.x;
    int i = blockIdx.x*256 + t;
    int v = (i < NN) ? g_cnt[i] : 0;
    s[t] = v; __syncthreads();
    for (int off = 1; off < 256; off <<= 1) {
        int x = (t >= off) ? s[t-off] : 0;
        __syncthreads(); s[t] += x; __syncthreads();
    }
    int excl = s[t] - v + g_bsum[blockIdx.x];
    if (i < NN) { g_base[i] = excl; g_cursor[i] = excl; }
}
__global__ void k_sids(const int* __restrict__ eidx) {
    int e = blockIdx.x*blockDim.x + threadIdx.x;
    if (e < NEE) {
        int src = eidx[e];
        int pos = atomicAdd(&g_cursor[eidx[NEE + e]], 1);
        g_eord[pos] = e;
        g_esrc[pos] = src;
    }
}

// ---------------- K: Q,K,V = x @ W^T + b  (f32x2, resident weights) -------
__global__ void __launch_bounds__(256) k_qkv(const float* __restrict__ x,
    const float* __restrict__ Wq, const float* __restrict__ bq,
    const float* __restrict__ Wk, const float* __restrict__ bk,
    const float* __restrict__ Wv, const float* __restrict__ bv)
{
    extern __shared__ float dynq[];
    float* sW = dynq;           // 3 * 64*64, [m][d*64 + j]
    float* sX = dynq + 12288;   // 128*64, [n][d ^ swz(n)]
    int t = threadIdx.x;
    int eg = t >> 4, cg = t & 15;
    int j0 = cg*4;
    int eswz = (eg & 7) << 2;
    const float* Ws[3] = {Wq, Wk, Wv};
    const float* bs[3] = {bq, bk, bv};
    float* outs[3] = {g_Q, g_K, g_V};

    #pragma unroll
    for (int m = 0; m < 3; m++)
        for (int idx = t; idx < 4096; idx += 256) {
            int j = idx >> 6, d = idx & 63;
            sW[m*4096 + d*64 + j] = Ws[m][j*64 + d];
        }
    ull biasm[3][2];
    #pragma unroll
    for (int m = 0; m < 3; m++) {
        float4 b = *(const float4*)&bs[m][j0];
        biasm[m][0] = pk(b.x, b.y); biasm[m][1] = pk(b.z, b.w);
    }
    __syncthreads();

    int ntiles = (NN + 127) / 128;   // 391
    for (int g = blockIdx.x; g < ntiles; g += gridDim.x) {
        int n0 = g*128;
        __syncthreads();
        #pragma unroll
        for (int k = 0; k < 8; k++) {
            int lin = t + k*256;
            int e = lin >> 4, d0 = (lin & 15)*4;
            int n = n0 + e;
            float4 v = (n < NN) ? *(const float4*)&x[(size_t)n*64 + d0]
                                : make_float4(0.f,0.f,0.f,0.f);
            int ds = d0 ^ (((e >> 3) & 7) << 2);
            *(float4*)&sX[e*64 + ds] = v;
        }
        __syncthreads();
        int abase = eg*8*64;
        #pragma unroll
        for (int m = 0; m < 3; m++) {
            ull acc[8][2];
            #pragma unroll
            for (int e = 0; e < 8; e++) { acc[e][0] = biasm[m][0]; acc[e][1] = biasm[m][1]; }
            const float* W = &sW[m*4096];
            #pragma unroll 4
            for (int d2 = 0; d2 < 64; d2 += 2) {
                int dx = d2 ^ eswz;
                float2 a2[8];
                #pragma unroll
                for (int i = 0; i < 8; i++) a2[i] = *(const float2*)&sX[abase + i*64 + dx];
                float4 w0 = *(const float4*)&W[d2*64 + j0];
                float4 w1 = *(const float4*)&W[(d2+1)*64 + j0];
                ull wp00 = pk(w0.x,w0.y), wp01 = pk(w0.z,w0.w);
                ull wp10 = pk(w1.x,w1.y), wp11 = pk(w1.z,w1.w);
                #pragma unroll
                for (int e = 0; e < 8; e++) {
                    ull ae0 = pk(a2[e].x, a2[e].x);
                    ull ae1 = pk(a2[e].y, a2[e].y);
                    fma2(acc[e][0], ae0, wp00); fma2(acc[e][1], ae0, wp01);
                    fma2(acc[e][0], ae1, wp10); fma2(acc[e][1], ae1, wp11);
                }
            }
            float* o = outs[m];
            #pragma unroll
            for (int e = 0; e < 8; e++) {
                int n = n0 + eg*8 + e;
                if (n < NN) {
                    float2 r0 = upk(acc[e][0]), r1 = upk(acc[e][1]);
                    *(float4*)&o[(size_t)n*64 + j0] = make_float4(r0.x, r0.y, r1.x, r1.y);
                }
            }
        }
    }
}

// ---------------- K: fused edge pipeline (80-edge tile, 3 CTAs/SM) ----------
// smem: weights 48KB + one 20KB tile buffer (ea -> score in place) = 68KB.
__global__ void __launch_bounds__(256, 3) k_edge(
    const float* __restrict__ ea, const int* __restrict__ eidx,
    const float* __restrict__ We, const float* __restrict__ be,
    const float* __restrict__ Aw,
    const float* __restrict__ Eo_w, const float* __restrict__ Eo_b,
    float* __restrict__ out_eh)
{
    extern __shared__ float dyn[];
    float* sWa = dyn;            // [d][p]  E1 cols permuted: colA(p) = (p>>3)*16 + (p&7)
    float* sWb = dyn + 4096;     // [d][p]  E2 cols (colA+8)
    float* sEo = dyn + 8192;     // [k][j]
    float* sB  = dyn + 12288;    // 80x64 tile: ea (phase1) then score (phase2), swizzled

    int t = threadIdx.x;
    int eg = t >> 4;             // 0..15 -> 5 edges each
    int cg = t & 15;             // 0..15
    int h  = cg >> 1, q = cg & 1;
    int j1  = h*16 + q*4;        // E1 col base; E2 at +8
    int sc0 = h*8 + q*4;         // score col base (phase1)
    int j0  = cg*4;              // eh col base (phase2)

    // per-thread edge rows, bases, swizzles
    int rw[5], ab[5], sw[5];
    #pragma unroll
    for (int i = 0; i < 5; i++) {
        rw[i] = eg*5 + i;
        ab[i] = rw[i]*64;
        sw[i] = ((rw[i] >> 3) & 7) << 2;
    }

    for (int idx = t; idx < 4096; idx += 256) {
        int d = idx & 63, p = idx >> 6;
        int colA = ((p >> 3) << 4) + (p & 7);
        sWa[d*64 + p] = We[colA*64 + d];
        sWb[d*64 + p] = We[(colA + 8)*64 + d];
        int j = idx >> 6, k = idx & 63;
        sEo[k*64 + j] = Eo_w[j*64 + k];
    }
    float4 bA = *(const float4*)&be[j1];
    float4 bB = *(const float4*)&be[j1 + 8];
    ull biasp[4] = { pk(bA.x,bA.y), pk(bA.z,bA.w), pk(bB.x,bB.y), pk(bB.z,bB.w) };
    float aw0 = Aw[(q*4+0)*8 + h], aw1 = Aw[(q*4+1)*8 + h];
    float aw2 = Aw[(q*4+2)*8 + h], aw3 = Aw[(q*4+3)*8 + h];
    float4 b2 = *(const float4*)&Eo_b[j0];
    ull bias2p[2] = { pk(b2.x,b2.y), pk(b2.z,b2.w) };

    float cs[4] = {0,0,0,0}, cq[4] = {0,0,0,0};

    for (int g = blockIdx.x; g < NEE/80; g += gridDim.x) {
        int e0 = g*80;
        __syncthreads();   // previous tile's phase-2 reads done before reload
        #pragma unroll
        for (int k = 0; k < 5; k++) {
            int lin = t + k*256;
            int e = lin >> 4, d0 = (lin & 15)*4;
            float4 v = *(const float4*)&ea[(size_t)(e0+e)*64 + d0];
            int ds = d0 ^ (((e >> 3) & 7) << 2);
            *(float4*)&sB[e*64 + ds] = v;
        }
        __syncthreads();

        // ---- phase 1 GEMM: E = ea @ We^T (5 edges x 8 cols) ----
        ull acc[5][4];
        #pragma unroll
        for (int e = 0; e < 5; e++) {
            acc[e][0]=biasp[0]; acc[e][1]=biasp[1]; acc[e][2]=biasp[2]; acc[e][3]=biasp[3];
        }
        #pragma unroll 4
        for (int d2 = 0; d2 < 64; d2 += 2) {
            float2 a2[5];
            #pragma unroll
            for (int i = 0; i < 5; i++) a2[i] = *(const float2*)&sB[ab[i] + (d2 ^ sw[i])];
            float4 wA0 = *(const float4*)&sWa[d2*64 + cg*4];
            float4 wB0 = *(const float4*)&sWb[d2*64 + cg*4];
            float4 wA1 = *(const float4*)&sWa[(d2+1)*64 + cg*4];
            float4 wB1 = *(const float4*)&sWb[(d2+1)*64 + cg*4];
            ull wa00 = pk(wA0.x,wA0.y), wa01 = pk(wA0.z,wA0.w);
            ull wb00 = pk(wB0.x,wB0.y), wb01 = pk(wB0.z,wB0.w);
            ull wa10 = pk(wA1.x,wA1.y), wa11 = pk(wA1.z,wA1.w);
            ull wb10 = pk(wB1.x,wB1.y), wb11 = pk(wB1.z,wB1.w);
            #pragma unroll
            for (int e = 0; e < 5; e++) {
                ull ae0 = pk(a2[e].x, a2[e].x);
                fma2(acc[e][0], ae0, wa00); fma2(acc[e][1], ae0, wa01);
                fma2(acc[e][2], ae0, wb00); fma2(acc[e][3], ae0, wb01);
                ull ae1 = pk(a2[e].y, a2[e].y);
                fma2(acc[e][0], ae1, wa10); fma2(acc[e][1], ae1, wa11);
                fma2(acc[e][2], ae1, wb10); fma2(acc[e][3], ae1, wb11);
            }
        }
        __syncthreads();   // all ea reads complete before in-place overwrite

        // ---- epilogue 1: score -> gmem + sB (in place), exp(clamp(a)) -> g_ex
        #pragma unroll
        for (int e = 0; e < 5; e++) {
            int E = e0 + rw[e];
            int src = eidx[E], dst = eidx[NEE + E];
            float2 A0 = upk(acc[e][0]), A1 = upk(acc[e][1]);
            float2 B0 = upk(acc[e][2]), B1 = upk(acc[e][3]);
            float s20 = A0.x*B0.x, s21 = A0.y*B0.y, s22 = A1.x*B1.x, s23 = A1.y*B1.y;
            float ss0 = copysignf(sqrtf(fabsf(s20)), s20);
            float ss1 = copysignf(sqrtf(fabsf(s21)), s21);
            float ss2 = copysignf(sqrtf(fabsf(s22)), s22);
            float ss3 = copysignf(sqrtf(fabsf(s23)), s23);
            float4 Kv = *(const float4*)&g_K[(size_t)src*64 + sc0];
            float4 Qv = *(const float4*)&g_Q[(size_t)dst*64 + sc0];
            float c0 = fmaxf(Kv.x + Qv.x + ss0, 0.f);
            float c1 = fmaxf(Kv.y + Qv.y + ss1, 0.f);
            float c2 = fmaxf(Kv.z + Qv.z + ss2, 0.f);
            float c3 = fmaxf(Kv.w + Qv.w + ss3, 0.f);
            float4 cv = make_float4(c0,c1,c2,c3);
            *(float4*)&g_score[(size_t)E*64 + sc0] = cv;
            *(float4*)&sB[ab[e] + (sc0 ^ sw[e])] = cv;
            float av = c0*aw0 + c1*aw1 + c2*aw2 + c3*aw3;
            av += __shfl_xor_sync(0xffffffffu, av, 1);
            if (q == 0) {
                av = fminf(fmaxf(av, -5.f), 5.f);
                g_ex[(size_t)E*8 + h] = expf(av);   // a in [-5,5]: exp safe, max-pass redundant
            }
        }
        __syncthreads();   // score tile complete

        // ---- phase 2 GEMM: eh = ea + score @ Eo^T (5 edges x 4 cols) ----
        ull acc2[5][2];
        #pragma unroll
        for (int e = 0; e < 5; e++) { acc2[e][0] = bias2p[0]; acc2[e][1] = bias2p[1]; }
        #pragma unroll 4
        for (int d2 = 0; d2 < 64; d2 += 2) {
            float2 a2[5];
            #pragma unroll
            for (int i = 0; i < 5; i++) a2[i] = *(const float2*)&sB[ab[i] + (d2 ^ sw[i])];
            float4 w0 = *(const float4*)&sEo[d2*64 + j0];
            float4 w1 = *(const float4*)&sEo[(d2+1)*64 + j0];
            ull wp00 = pk(w0.x,w0.y), wp01 = pk(w0.z,w0.w);
            ull wp10 = pk(w1.x,w1.y), wp11 = pk(w1.z,w1.w);
            #pragma unroll
            for (int e = 0; e < 5; e++) {
                ull ae0 = pk(a2[e].x, a2[e].x);
                ull ae1 = pk(a2[e].y, a2[e].y);
                fma2(acc2[e][0], ae0, wp00); fma2(acc2[e][1], ae0, wp01);
                fma2(acc2[e][0], ae1, wp10); fma2(acc2[e][1], ae1, wp11);
            }
        }
        // ---- epilogue 2: residual re-read from gmem, store eh, BN sums ----
        #pragma unroll
        for (int e = 0; e < 5; e++) {
            size_t E = (size_t)(e0 + rw[e]);
            float2 r0 = upk(acc2[e][0]), r1 = upk(acc2[e][1]);
            float4 q0 = *(const float4*)&ea[E*64 + j0];
            float o0 = r0.x + q0.x, o1 = r0.y + q0.y;
            float o2 = r1.x + q0.z, o3 = r1.y + q0.w;
            *(float4*)&out_eh[E*64 + j0] = make_float4(o0,o1,o2,o3);
            cs[0]+=o0; cs[1]+=o1; cs[2]+=o2; cs[3]+=o3;
            cq[0]+=o0*o0; cq[1]+=o1*o1; cq[2]+=o2*o2; cq[3]+=o3*o3;
        }
    }
    // BN sums reduce
    __syncthreads();
    float* red = sB;
    if (t < 128) red[t] = 0.f;
    __syncthreads();
    #pragma unroll
    for (int i = 0; i < 4; i++) {
        atomicAdd(&red[j0 + i], cs[i]);
        atomicAdd(&red[64 + j0 + i], cq[i]);
    }
    __syncthreads();
    if (t < 64) {
        atomicAdd(&g_sums[t],      (double)red[t]);
        atomicAdd(&g_sums[64 + t], (double)red[64 + t]);
    }
}

// ---------------- K: per-node attention accumulate (single pass) -----------
__global__ void __launch_bounds__(256) k_nattn() {
    int warp = threadIdx.x >> 5, lane = threadIdx.x & 31;
    int n = blockIdx.x*8 + warp;
    int c2 = lane*2;
    int deg = g_cnt[n];
    int base = g_base[n];
    if (deg == 0) {
        *(float2*)&g_oV[(size_t)n*64 + c2]     = make_float2(0.f, 0.f);
        *(float2*)&g_rowAcc[(size_t)n*64 + c2] = make_float2(0.f, 0.f);
        return;
    }
    int hh = lane >> 2;   // head owning cols c2, c2+1
    float dnacc = 0.f;
    float av0=0.f, av1=0.f, ar0=0.f, ar1=0.f;
    #pragma unroll 2
    for (int k = 0; k < deg; k++) {
        int idx = base + k;
        int eid = g_eord[idx];
        int src = g_esrc[idx];
        float ex = g_ex[(size_t)eid*8 + hh];
        dnacc += ex;
        float2 v = *(const float2*)&g_V[(size_t)src*64 + c2];
        float2 s = *(const float2*)&g_score[(size_t)eid*64 + c2];
        av0 = fmaf(v.x, ex, av0); av1 = fmaf(v.y, ex, av1);
        ar0 = fmaf(s.x, ex, ar0); ar1 = fmaf(s.y, ex, ar1);
    }
    float myr = 1.f / (dnacc + 1e-16f);
    *(float2*)&g_oV[(size_t)n*64 + c2]     = make_float2(av0*myr, av1*myr);
    *(float2*)&g_rowAcc[(size_t)n*64 + c2] = make_float2(ar0*myr, ar1*myr);
}

// ---------------- K: rowV einsum + deg + No gemm + residual + BN1 sums ----
__global__ void __launch_bounds__(256) k_node1(
    const float* __restrict__ x, const float* __restrict__ log_deg,
    const float* __restrict__ VeRow, const float* __restrict__ deg_coef,
    const float* __restrict__ No_w, const float* __restrict__ No_b)
{
    __shared__ __align__(16) float sNoT[64*64];
    __shared__ float sVe[512];
    __shared__ float sDC0[64], sDC1[64], sNob[64];
    __shared__ __align__(16) float sNH[16][64];
    __shared__ __align__(16) float sRA[16][64];
    int t = threadIdx.x;
    for (int i = t; i < 64*64; i += 256)
        sNoT[(i&63)*64 + (i>>6)] = No_w[i];
    for (int i = t; i < 512; i += 256) sVe[i] = VeRow[i];
    if (t < 64) { sDC0[t]=deg_coef[t*2]; sDC1[t]=deg_coef[t*2+1]; sNob[t]=No_b[t]; }
    __syncthreads();

    float cs0=0,cs1=0,cs2=0,cs3=0, cq0=0,cq1=0,cq2=0,cq3=0;
    int ngroups = NN/16;
    for (int g = blockIdx.x; g < ngroups; g += gridDim.x) {
        int n0 = g*16;
        for (int i = t; i < 16*64; i += 256)
            sRA[i>>6][i&63] = g_rowAcc[(size_t)(n0 + (i>>6))*64 + (i&63)];
        __syncthreads();
        int j = t & 63, h = j >> 3;
        #pragma unroll
        for (int qq = 0; qq < 4; qq++) {
            int le = (t >> 6) + qq*4;
            int n = n0 + le;
            float rv = 0.f;
            #pragma unroll
            for (int d = 0; d < 8; d++)
                rv = fmaf(sRA[le][h*8+d], sVe[d*64 + j], rv);
            float nh0 = g_oV[(size_t)n*64 + j] + rv;
            float ld = log_deg[n];
            sNH[le][j] = nh0 * (sDC0[j] + ld*sDC1[j]);
        }
        __syncthreads();
        {
            int j4 = (t & 15) * 4;
            int le = t >> 4;
            int n = n0 + le;
            float4 acc = make_float4(sNob[j4], sNob[j4+1], sNob[j4+2], sNob[j4+3]);
            #pragma unroll 8
            for (int d = 0; d < 64; d++) {
                float a = sNH[le][d];
                float4 w = *(const float4*)&sNoT[d*64 + j4];
                acc.x = fmaf(a,w.x,acc.x); acc.y = fmaf(a,w.y,acc.y);
                acc.z = fmaf(a,w.z,acc.z); acc.w = fmaf(a,w.w,acc.w);
            }
            float4 xr = *(const float4*)&x[(size_t)n*64 + j4];
            acc.x += xr.x; acc.y += xr.y; acc.z += xr.z; acc.w += xr.w;
            *(float4*)&g_nh1[(size_t)n*64 + j4] = acc;
            cs0 += acc.x; cs1 += acc.y; cs2 += acc.z; cs3 += acc.w;
            cq0 += acc.x*acc.x; cq1 += acc.y*acc.y; cq2 += acc.z*acc.z; cq3 += acc.w*acc.w;
        }
        __syncthreads();
    }
    float* red = &sRA[0][0];
    if (t < 128) red[t] = 0.f;
    __syncthreads();
    int j4 = (t & 15) * 4;
    atomicAdd(&red[j4+0], cs0); atomicAdd(&red[j4+1], cs1);
    atomicAdd(&red[j4+2], cs2); atomicAdd(&red[j4+3], cs3);
    atomicAdd(&red[64+j4+0], cq0); atomicAdd(&red[64+j4+1], cq1);
    atomicAdd(&red[64+j4+2], cq2); atomicAdd(&red[64+j4+3], cq3);
    __syncthreads();
    if (t < 64) {
        atomicAdd(&g_sums[128+t], (double)red[t]);
        atomicAdd(&g_sums[192+t], (double)red[64+t]);
    }
}

// ---------------- K: BN params (edge, node1) ----------------
__global__ void k_bnp1(const float* __restrict__ g1e, const float* __restrict__ b1e,
                       const float* __restrict__ g1n, const float* __restrict__ b1n) {
    int t = threadIdx.x;
    if (t < 64) {
        double mu = g_sums[t] / (double)NEE;
        double var = g_sums[64+t] / (double)NEE - mu*mu;
        float sc = (float)(1.0/sqrt(var + 1e-5)) * g1e[t];
        g_bnp[t] = sc; g_bnp[64+t] = b1e[t] - (float)mu*sc;
    } else {
        int j = t - 64;
        double mu = g_sums[128+j] / (double)NN;
        double var = g_sums[192+j] / (double)NN - mu*mu;
        float sc = (float)(1.0/sqrt(var + 1e-5)) * g1n[j];
        g_bnp[128+j] = sc; g_bnp[192+j] = b1n[j] - (float)mu*sc;
    }
}

// ---------------- K: BN1 apply + MLP + residual + BN2 sums ----------------
__global__ void __launch_bounds__(256) k_mlp(
    const float* __restrict__ W1, const float* __restrict__ b1f,
    const float* __restrict__ W2, const float* __restrict__ b2f)
{
    extern __shared__ float dynm[];
    float* sW1 = dynm;           // [d][k] 64*128
    float* sW2 = dynm + 8192;    // [k][j] 128*64
    float* sHf = dynm + 16384;   // [le][k] 16*128
    float* sBv = dynm + 18432;   // [le][j] 16*64
    __shared__ float sb1[128];
    __shared__ float sb2[64], sScale[64], sShift[64];
    int t = threadIdx.x;
    if (t < 128) sb1[t] = b1f[t];
    if (t < 64) { sb2[t]=b2f[t]; sScale[t]=g_bnp[128+t]; sShift[t]=g_bnp[192+t]; }
    for (int i = t; i < 128*64; i += 256) {
        int k = i >> 6, d = i & 63;
        sW1[d*128 + k] = W1[i];               // W1[k,d] -> [d][k]
        int j = i >> 7, k2 = i & 127;
        sW2[k2*64 + j] = W2[i];               // W2[j,k] -> [k][j]
    }

    float cs0=0,cs1=0,cs2=0,cs3=0, cq0=0,cq1=0,cq2=0,cq3=0;
    int ngroups = NN/16;
    for (int g = blockIdx.x; g < ngroups; g += gridDim.x) {
        int n0 = g*16;
        __syncthreads();
        for (int i = t; i < 16*64; i += 256) {
            int le = i >> 6, j = i & 63;
            sBv[le*64 + j] = g_nh1[(size_t)(n0+le)*64 + j]*sScale[j] + sShift[j];
        }
        __syncthreads();
        {   // h = relu(bnv @ W1^T + b1)
            int k4 = (t & 31) * 4;
            int le0 = t >> 5;
            float4 acc0 = make_float4(sb1[k4], sb1[k4+1], sb1[k4+2], sb1[k4+3]);
            float4 acc1 = acc0;
            #pragma unroll 8
            for (int d = 0; d < 64; d++) {
                float4 w = *(const float4*)&sW1[d*128 + k4];
                float a0 = sBv[le0*64 + d], a1 = sBv[(le0+8)*64 + d];
                acc0.x = fmaf(a0,w.x,acc0.x); acc0.y = fmaf(a0,w.y,acc0.y);
                acc0.z = fmaf(a0,w.z,acc0.z); acc0.w = fmaf(a0,w.w,acc0.w);
                acc1.x = fmaf(a1,w.x,acc1.x); acc1.y = fmaf(a1,w.y,acc1.y);
                acc1.z = fmaf(a1,w.z,acc1.z); acc1.w = fmaf(a1,w.w,acc1.w);
            }
            acc0.x=fmaxf(acc0.x,0.f); acc0.y=fmaxf(acc0.y,0.f); acc0.z=fmaxf(acc0.z,0.f); acc0.w=fmaxf(acc0.w,0.f);
            acc1.x=fmaxf(acc1.x,0.f); acc1.y=fmaxf(acc1.y,0.f); acc1.z=fmaxf(acc1.z,0.f); acc1.w=fmaxf(acc1.w,0.f);
            *(float4*)&sHf[le0*128 + k4]     = acc0;
            *(float4*)&sHf[(le0+8)*128 + k4] = acc1;
        }
        __syncthreads();
        {   // nh3 = bnv + h @ W2^T + b2
            int j4 = (t & 15) * 4;
            int le = t >> 4;
            int n = n0 + le;
            float4 acc = make_float4(sb2[j4], sb2[j4+1], sb2[j4+2], sb2[j4+3]);
            #pragma unroll 8
            for (int k = 0; k < 128; k++) {
                float a = sHf[le*128 + k];
                float4 w = *(const float4*)&sW2[k*64 + j4];
                acc.x = fmaf(a,w.x,acc.x); acc.y = fmaf(a,w.y,acc.y);
                acc.z = fmaf(a,w.z,acc.z); acc.w = fmaf(a,w.w,acc.w);
            }
            acc.x += sBv[le*64 + j4+0]; acc.y += sBv[le*64 + j4+1];
            acc.z += sBv[le*64 + j4+2]; acc.w += sBv[le*64 + j4+3];
            *(float4*)&g_nh3[(size_t)n*64 + j4] = acc;
            cs0 += acc.x; cs1 += acc.y; cs2 += acc.z; cs3 += acc.w;
            cq0 += acc.x*acc.x; cq1 += acc.y*acc.y; cq2 += acc.z*acc.z; cq3 += acc.w*acc.w;
        }
    }
    __syncthreads();
    float* red = sHf;
    if (t < 128) red[t] = 0.f;
    __syncthreads();
    int j4 = (t & 15) * 4;
    atomicAdd(&red[j4+0], cs0); atomicAdd(&red[j4+1], cs1);
    atomicAdd(&red[j4+2], cs2); atomicAdd(&red[j4+3], cs3);
    atomicAdd(&red[64+j4+0], cq0); atomicAdd(&red[64+j4+1], cq1);
    atomicAdd(&red[64+j4+2], cq2); atomicAdd(&red[64+j4+3], cq3);
    __syncthreads();
    if (t < 64) {
        atomicAdd(&g_sums[256+t], (double)red[t]);
        atomicAdd(&g_sums[320+t], (double)red[64+t]);
    }
}

// ---------------- K: BN2 params ----------------
__global__ void k_bnp2(const float* __restrict__ g2, const float* __restrict__ beta2) {
    int t = threadIdx.x;
    double mu = g_sums[256+t] / (double)NN;
    double var = g_sums[320+t] / (double)NN - mu*mu;
    float sc = (float)(1.0/sqrt(var + 1e-5)) * g2[t];
    g_bnp[256+t] = sc; g_bnp[320+t] = beta2[t] - (float)mu*sc;
}

// ---------------- K: apply BN2 (nodes) + edge BN (in place) ----------------
__global__ void k_finish(float* __restrict__ out) {
    const int NODE4 = NN*16;
    const int TOT4 = NODE4 + NEE*16;
    int q = blockIdx.x*blockDim.x + threadIdx.x;
    if (q >= TOT4) return;
    int j = (q*4) & 63;
    if (q < NODE4) {
        float4 v = *(const float4*)&g_nh3[(size_t)q*4];
        float4 sc = *(const float4*)&g_bnp[256+j];
        float4 sh = *(const float4*)&g_bnp[320+j];
        float4 r;
        r.x = v.x*sc.x + sh.x; r.y = v.y*sc.y + sh.y;
        r.z = v.z*sc.z + sh.z; r.w = v.w*sc.w + sh.w;
        ((float4*)out)[q] = r;
    } else {
        float4 v = ((const float4*)out)[q];
        float4 sc = *(const float4*)&g_bnp[j];
        float4 sh = *(const float4*)&g_bnp[64+j];
        float4 r;
        r.x = v.x*sc.x + sh.x; r.y = v.y*sc.y + sh.y;
        r.z = v.z*sc.z + sh.z; r.w = v.w*sc.w + sh.w;
        ((float4*)out)[q] = r;
    }
}

// ---------------- launch ----------------
extern "C" void kernel_launch(void* const* d_in, const int* in_sizes, int n_in,
                              void* d_out, int out_size) {
    const float* x        = (const float*)d_in[0];
    const float* ea       = (const float*)d_in[1];
    const float* log_deg  = (const float*)d_in[2];
    const int*   eidx     = (const int*)d_in[3];
    const float* Wq = (const float*)d_in[4];  const float* bq = (const float*)d_in[5];
    const float* Wk = (const float*)d_in[6];  const float* bk = (const float*)d_in[7];
    const float* Wv = (const float*)d_in[8];  const float* bv = (const float*)d_in[9];
    const float* We = (const float*)d_in[10]; const float* be = (const float*)d_in[11];
    const float* Aw = (const float*)d_in[12]; const float* VeRow = (const float*)d_in[13];
    const float* deg_coef = (const float*)d_in[14];
    const float* No_w = (const float*)d_in[15]; const float* No_b = (const float*)d_in[16];
    const float* Eo_w = (const float*)d_in[17]; const float* Eo_b = (const float*)d_in[18];
    const float* W1 = (const float*)d_in[19]; const float* b1f = (const float*)d_in[20];
    const float* W2 = (const float*)d_in[21]; const float* b2f = (const float*)d_in[22];
    const float* g1n = (const float*)d_in[23]; const float* b1n = (const float*)d_in[24];
    const float* g1e = (const float*)d_in[25]; const float* b1e = (const float*)d_in[26];
    const float* g2  = (const float*)d_in[27]; const float* beta2 = (const float*)d_in[28];

    float* out = (float*)d_out;
    float* out_eh = out + (size_t)NN*64;

    const int QKV_SMEM  = (12288 + 8192) * 4;   // 80 KB
    const int EDGE_SMEM = 17408 * 4;            // 68 KB -> 3 CTAs/SM
    const int MLP_SMEM  = 19456 * 4;            // 76 KB
    cudaFuncSetAttribute(k_qkv,  cudaFuncAttributeMaxDynamicSharedMemorySize, QKV_SMEM);
    cudaFuncSetAttribute(k_edge, cudaFuncAttributeMaxDynamicSharedMemorySize, EDGE_SMEM);
    cudaFuncSetAttribute(k_mlp,  cudaFuncAttributeMaxDynamicSharedMemorySize, MLP_SMEM);

    // order: k_edge at launch index 3 so ncu's fixed capture lands on it
    k_qkv   <<<391, 256, QKV_SMEM>>>(x, Wq, bq, Wk, bk, Wv, bv);     // 0
    k_init  <<<196, 256>>>();                                        // 1
    k_hist  <<<3125, 256>>>(eidx);                                   // 2
    k_edge  <<<4440, 256, EDGE_SMEM>>>(ea, eidx, We, be, Aw, Eo_w, Eo_b, out_eh); // 3
    k_scan1 <<<196, 256>>>();                                        // 4
    k_scan2 <<<1, 256>>>();                                          // 5
    k_scan3 <<<196, 256>>>();                                        // 6
    k_sids  <<<3125, 256>>>(eidx);                                   // 7
    k_nattn <<<6250, 256>>>();                                       // 8
    k_node1 <<<592, 256>>>(x, log_deg, VeRow, deg_coef, No_w, No_b); // 9
    k_bnp1  <<<1, 128>>>(g1e, b1e, g1n, b1n);                        // 10
    k_mlp   <<<592, 256, MLP_SMEM>>>(W1, b1f, W2, b2f);              // 11
    k_bnp2  <<<1, 64>>>(g2, beta2);                                  // 12
    k_finish<<<53125, 256>>>(out);                                   // 13
}

// round 17
// speedup vs baseline: 1.0893x; 1.0856x over previous
#include <cuda_runtime.h>
#include <math.h>

#define NN 50000
#define NEE 800000

typedef unsigned long long ull;

// ---------------- scratch ----------------
__device__ float g_Q[NN*64];
__device__ float g_K[NN*64];
__device__ float g_V[NN*64];
__device__ float g_score[(size_t)NEE*64];   // edge-id ordered
__device__ float g_ex[NEE*8];               // exp(clamp(a)) per (edge, head)
__device__ float g_oV[NN*64];
__device__ float g_rowAcc[NN*64];
__device__ float g_nh1[NN*64];
__device__ float g_nh3[NN*64];
__device__ double g_sums[6*64];
__device__ float g_bnp[6*64];
// CSR by dst
__device__ int g_cnt[NN];
__device__ int g_base[NN];
__device__ int g_cursor[NN];
__device__ int g_eord[NEE];
__device__ int g_esrc[NEE];
__device__ int g_bsum[256];

// ---------------- f32x2 helpers ----------------
__device__ __forceinline__ ull pk(float x, float y) {
    ull r; asm("mov.b64 %0,{%1,%2};" : "=l"(r) : "f"(x), "f"(y)); return r;
}
__device__ __forceinline__ void fma2(ull &d, ull a, ull b) {
    asm("fma.rn.f32x2 %0,%1,%2,%0;" : "+l"(d) : "l"(a), "l"(b));
}
__device__ __forceinline__ float2 upk(ull v) {
    float2 r; asm("mov.b64 {%0,%1},%2;" : "=f"(r.x), "=f"(r.y) : "l"(v)); return r;
}

// ---------------- K: init ----------------
__global__ void k_init() {
    int i = blockIdx.x*blockDim.x + threadIdx.x;
    if (i < NN) g_cnt[i] = 0;
    if (i < 6*64) g_sums[i] = 0.0;
}

// ---------------- CSR build ----------------
__global__ void k_hist(const int* __restrict__ eidx) {
    int e = blockIdx.x*blockDim.x + threadIdx.x;
    if (e < NEE) atomicAdd(&g_cnt[eidx[NEE + e]], 1);
}
__global__ void k_scan1() {
    __shared__ int sred[256];
    int t = threadIdx.x;
    int i = blockIdx.x*256 + t;
    int v = (i < NN) ? g_cnt[i] : 0;
    sred[t] = v; __syncthreads();
    for (int s = 128; s > 0; s >>= 1) { if (t < s) sred[t] += sred[t+s]; __syncthreads(); }
    if (t == 0) g_bsum[blockIdx.x] = sred[0];
}
__global__ void k_scan2() {
    __shared__ int s[256];
    int t = threadIdx.x;
    int v = (t < 196) ? g_bsum[t] : 0;
    s[t] = v; __syncthreads();
    for (int off = 1; off < 256; off <<= 1) {
        int x = (t >= off) ? s[t-off] : 0;
        __syncthreads(); s[t] += x; __syncthreads();
    }
    if (t < 196) g_bsum[t] = s[t] - v;
}
__global__ void k_scan3() {
    __shared__ int s[256];
    int t = threadIdx.x;
    int i = blockIdx.x*256 + t;
    int v = (i < NN) ? g_cnt[i] : 0;
    s[t] = v; __syncthreads();
    for (int off = 1; off < 256; off <<= 1) {
        int x = (t >= off) ? s[t-off] : 0;
        __syncthreads(); s[t] += x; __syncthreads();
    }
    int excl = s[t] - v + g_bsum[blockIdx.x];
    if (i < NN) { g_base[i] = excl; g_cursor[i] = excl; }
}
__global__ void k_sids(const int* __restrict__ eidx) {
    int e = blockIdx.x*blockDim.x + threadIdx.x;
    if (e < NEE) {
        int src = eidx[e];
        int pos = atomicAdd(&g_cursor[eidx[NEE + e]], 1);
        g_eord[pos] = e;
        g_esrc[pos] = src;
    }
}

// ---------------- K: Q,K,V = x @ W^T + b  (f32x2, resident weights) -------
__global__ void __launch_bounds__(256) k_qkv(const float* __restrict__ x,
    const float* __restrict__ Wq, const float* __restrict__ bq,
    const float* __restrict__ Wk, const float* __restrict__ bk,
    const float* __restrict__ Wv, const float* __restrict__ bv)
{
    extern __shared__ float dynq[];
    float* sW = dynq;           // 3 * 64*64, [m][d*64 + j]
    float* sX = dynq + 12288;   // 128*64, [n][d ^ swz(n)]
    int t = threadIdx.x;
    int eg = t >> 4, cg = t & 15;
    int j0 = cg*4;
    int eswz = (eg & 7) << 2;
    const float* Ws[3] = {Wq, Wk, Wv};
    const float* bs[3] = {bq, bk, bv};
    float* outs[3] = {g_Q, g_K, g_V};

    #pragma unroll
    for (int m = 0; m < 3; m++)
        for (int idx = t; idx < 4096; idx += 256) {
            int j = idx >> 6, d = idx & 63;
            sW[m*4096 + d*64 + j] = Ws[m][j*64 + d];
        }
    ull biasm[3][2];
    #pragma unroll
    for (int m = 0; m < 3; m++) {
        float4 b = *(const float4*)&bs[m][j0];
        biasm[m][0] = pk(b.x, b.y); biasm[m][1] = pk(b.z, b.w);
    }
    __syncthreads();

    int ntiles = (NN + 127) / 128;   // 391
    for (int g = blockIdx.x; g < ntiles; g += gridDim.x) {
        int n0 = g*128;
        __syncthreads();
        #pragma unroll
        for (int k = 0; k < 8; k++) {
            int lin = t + k*256;
            int e = lin >> 4, d0 = (lin & 15)*4;
            int n = n0 + e;
            float4 v = (n < NN) ? *(const float4*)&x[(size_t)n*64 + d0]
                                : make_float4(0.f,0.f,0.f,0.f);
            int ds = d0 ^ (((e >> 3) & 7) << 2);
            *(float4*)&sX[e*64 + ds] = v;
        }
        __syncthreads();
        int abase = eg*8*64;
        #pragma unroll
        for (int m = 0; m < 3; m++) {
            ull acc[8][2];
            #pragma unroll
            for (int e = 0; e < 8; e++) { acc[e][0] = biasm[m][0]; acc[e][1] = biasm[m][1]; }
            const float* W = &sW[m*4096];
            #pragma unroll 4
            for (int d2 = 0; d2 < 64; d2 += 2) {
                int dx = d2 ^ eswz;
                float2 a2[8];
                #pragma unroll
                for (int i = 0; i < 8; i++) a2[i] = *(const float2*)&sX[abase + i*64 + dx];
                float4 w0 = *(const float4*)&W[d2*64 + j0];
                float4 w1 = *(const float4*)&W[(d2+1)*64 + j0];
                ull wp00 = pk(w0.x,w0.y), wp01 = pk(w0.z,w0.w);
                ull wp10 = pk(w1.x,w1.y), wp11 = pk(w1.z,w1.w);
                #pragma unroll
                for (int e = 0; e < 8; e++) {
                    ull ae0 = pk(a2[e].x, a2[e].x);
                    ull ae1 = pk(a2[e].y, a2[e].y);
                    fma2(acc[e][0], ae0, wp00); fma2(acc[e][1], ae0, wp01);
                    fma2(acc[e][0], ae1, wp10); fma2(acc[e][1], ae1, wp11);
                }
            }
            float* o = outs[m];
            #pragma unroll
            for (int e = 0; e < 8; e++) {
                int n = n0 + eg*8 + e;
                if (n < NN) {
                    float2 r0 = upk(acc[e][0]), r1 = upk(acc[e][1]);
                    *(float4*)&o[(size_t)n*64 + j0] = make_float4(r0.x, r0.y, r1.x, r1.y);
                }
            }
        }
    }
}

// ---------------- K: edge phase 1 — E GEMM -> score -> exp(clamp(a)) -------
// smem: Wa 16KB + Wb 16KB + A tile 32KB = 64KB. 8 edges x 8 cols per thread.
__global__ void __launch_bounds__(256) k_edge1(
    const float* __restrict__ ea, const int* __restrict__ eidx,
    const float* __restrict__ We, const float* __restrict__ be,
    const float* __restrict__ Aw)
{
    extern __shared__ float dyn[];
    float* sWa = dyn;            // [d][p]  E1 cols permuted: colA(p) = (p>>3)*16 + (p&7)
    float* sWb = dyn + 4096;     // [d][p]  E2 cols (colA+8)
    float* sA  = dyn + 8192;     // [e][d ^ swz(e)]  ea tile (128x64)

    int t = threadIdx.x;
    int eg = t >> 4;             // 0..15 -> 8 edges each
    int cg = t & 15;             // 0..15
    int h  = cg >> 1, q = cg & 1;
    int j1  = h*16 + q*4;        // E1 col base; E2 at +8
    int sc0 = h*8 + q*4;         // score col base
    int eswz = (eg & 7) << 2;

    for (int idx = t; idx < 4096; idx += 256) {
        int d = idx & 63, p = idx >> 6;
        int colA = ((p >> 3) << 4) + (p & 7);
        sWa[d*64 + p] = We[colA*64 + d];
        sWb[d*64 + p] = We[(colA + 8)*64 + d];
    }
    float4 bA = *(const float4*)&be[j1];
    float4 bB = *(const float4*)&be[j1 + 8];
    ull biasp[4] = { pk(bA.x,bA.y), pk(bA.z,bA.w), pk(bB.x,bB.y), pk(bB.z,bB.w) };
    float aw0 = Aw[(q*4+0)*8 + h], aw1 = Aw[(q*4+1)*8 + h];
    float aw2 = Aw[(q*4+2)*8 + h], aw3 = Aw[(q*4+3)*8 + h];
    int abase = eg*8*64;
    __syncthreads();

    for (int g = blockIdx.x; g < NEE/128; g += gridDim.x) {
        int e0 = g*128;
        __syncthreads();
        #pragma unroll
        for (int k = 0; k < 8; k++) {
            int lin = t + k*256;
            int e = lin >> 4, d0 = (lin & 15)*4;
            float4 v = *(const float4*)&ea[(size_t)(e0+e)*64 + d0];
            int ds = d0 ^ (((e >> 3) & 7) << 2);
            *(float4*)&sA[e*64 + ds] = v;
        }
        __syncthreads();

        ull acc[8][4];
        #pragma unroll
        for (int e = 0; e < 8; e++) {
            acc[e][0]=biasp[0]; acc[e][1]=biasp[1]; acc[e][2]=biasp[2]; acc[e][3]=biasp[3];
        }
        #pragma unroll 4
        for (int d2 = 0; d2 < 64; d2 += 2) {
            int dx = d2 ^ eswz;
            float2 a2[8];
            #pragma unroll
            for (int i = 0; i < 8; i++) a2[i] = *(const float2*)&sA[abase + i*64 + dx];
            float4 wA0 = *(const float4*)&sWa[d2*64 + cg*4];
            float4 wB0 = *(const float4*)&sWb[d2*64 + cg*4];
            float4 wA1 = *(const float4*)&sWa[(d2+1)*64 + cg*4];
            float4 wB1 = *(const float4*)&sWb[(d2+1)*64 + cg*4];
            ull wa00 = pk(wA0.x,wA0.y), wa01 = pk(wA0.z,wA0.w);
            ull wb00 = pk(wB0.x,wB0.y), wb01 = pk(wB0.z,wB0.w);
            ull wa10 = pk(wA1.x,wA1.y), wa11 = pk(wA1.z,wA1.w);
            ull wb10 = pk(wB1.x,wB1.y), wb11 = pk(wB1.z,wB1.w);
            #pragma unroll
            for (int e = 0; e < 8; e++) {
                ull ae0 = pk(a2[e].x, a2[e].x);
                fma2(acc[e][0], ae0, wa00); fma2(acc[e][1], ae0, wa01);
                fma2(acc[e][2], ae0, wb00); fma2(acc[e][3], ae0, wb01);
                ull ae1 = pk(a2[e].y, a2[e].y);
                fma2(acc[e][0], ae1, wa10); fma2(acc[e][1], ae1, wa11);
                fma2(acc[e][2], ae1, wb10); fma2(acc[e][3], ae1, wb11);
            }
        }
        #pragma unroll
        for (int e = 0; e < 8; e++) {
            int E = e0 + eg*8 + e;
            int src = eidx[E], dst = eidx[NEE + E];
            float2 A0 = upk(acc[e][0]), A1 = upk(acc[e][1]);
            float2 B0 = upk(acc[e][2]), B1 = upk(acc[e][3]);
            float s20 = A0.x*B0.x, s21 = A0.y*B0.y, s22 = A1.x*B1.x, s23 = A1.y*B1.y;
            float ss0 = copysignf(sqrtf(fabsf(s20)), s20);
            float ss1 = copysignf(sqrtf(fabsf(s21)), s21);
            float ss2 = copysignf(sqrtf(fabsf(s22)), s22);
            float ss3 = copysignf(sqrtf(fabsf(s23)), s23);
            float4 Kv = *(const float4*)&g_K[(size_t)src*64 + sc0];
            float4 Qv = *(const float4*)&g_Q[(size_t)dst*64 + sc0];
            float c0 = fmaxf(Kv.x + Qv.x + ss0, 0.f);
            float c1 = fmaxf(Kv.y + Qv.y + ss1, 0.f);
            float c2 = fmaxf(Kv.z + Qv.z + ss2, 0.f);
            float c3 = fmaxf(Kv.w + Qv.w + ss3, 0.f);
            *(float4*)&g_score[(size_t)E*64 + sc0] = make_float4(c0,c1,c2,c3);
            float av = c0*aw0 + c1*aw1 + c2*aw2 + c3*aw3;
            av += __shfl_xor_sync(0xffffffffu, av, 1);
            if (q == 0) {
                av = fminf(fmaxf(av, -5.f), 5.f);
                g_ex[(size_t)E*8 + h] = expf(av);   // a in [-5,5]: exp safe, max-pass redundant
            }
        }
    }
}

// ---------------- K: edge phase 2 — eh = ea + score @ Eo^T + b (+BN sums) --
// smem: Eo 16KB + score tile 32KB = 48KB -> 3 CTAs/SM. 8 edges x 4 cols/thread.
__global__ void __launch_bounds__(256, 3) k_edge2(
    const float* __restrict__ ea,
    const float* __restrict__ Eo_w, const float* __restrict__ Eo_b,
    float* __restrict__ out_eh)
{
    extern __shared__ float dyn2[];
    float* sEo = dyn2;           // [k][j] 16KB
    float* sS  = dyn2 + 4096;    // [e][d ^ swz(e)] score tile (128x64) 32KB

    int t = threadIdx.x;
    int eg = t >> 4;             // 0..15 -> 8 edges each
    int cg = t & 15;             // 0..15
    int j0 = cg*4;
    int eswz = (eg & 7) << 2;

    for (int idx = t; idx < 4096; idx += 256) {
        int j = idx >> 6, k = idx & 63;
        sEo[k*64 + j] = Eo_w[j*64 + k];
    }
    float4 b2 = *(const float4*)&Eo_b[j0];
    ull bias2p[2] = { pk(b2.x,b2.y), pk(b2.z,b2.w) };

    float cs[4] = {0,0,0,0}, cq[4] = {0,0,0,0};
    int abase = eg*8*64;
    __syncthreads();

    for (int g = blockIdx.x; g < NEE/128; g += gridDim.x) {
        int e0 = g*128;
        __syncthreads();
        #pragma unroll
        for (int k = 0; k < 8; k++) {
            int lin = t + k*256;
            int e = lin >> 4, d0 = (lin & 15)*4;
            float4 v = *(const float4*)&g_score[(size_t)(e0+e)*64 + d0];
            int ds = d0 ^ (((e >> 3) & 7) << 2);
            *(float4*)&sS[e*64 + ds] = v;
        }
        __syncthreads();

        ull acc2[8][2];
        #pragma unroll
        for (int e = 0; e < 8; e++) { acc2[e][0] = bias2p[0]; acc2[e][1] = bias2p[1]; }
        #pragma unroll 4
        for (int d2 = 0; d2 < 64; d2 += 2) {
            int dx = d2 ^ eswz;
            float2 a2[8];
            #pragma unroll
            for (int i = 0; i < 8; i++) a2[i] = *(const float2*)&sS[abase + i*64 + dx];
            float4 w0 = *(const float4*)&sEo[d2*64 + j0];
            float4 w1 = *(const float4*)&sEo[(d2+1)*64 + j0];
            ull wp00 = pk(w0.x,w0.y), wp01 = pk(w0.z,w0.w);
            ull wp10 = pk(w1.x,w1.y), wp11 = pk(w1.z,w1.w);
            #pragma unroll
            for (int e = 0; e < 8; e++) {
                ull ae0 = pk(a2[e].x, a2[e].x);
                ull ae1 = pk(a2[e].y, a2[e].y);
                fma2(acc2[e][0], ae0, wp00); fma2(acc2[e][1], ae0, wp01);
                fma2(acc2[e][0], ae1, wp10); fma2(acc2[e][1], ae1, wp11);
            }
        }
        #pragma unroll
        for (int e = 0; e < 8; e++) {
            size_t E = (size_t)(e0 + eg*8 + e);
            float2 r0 = upk(acc2[e][0]), r1 = upk(acc2[e][1]);
            float4 q0 = *(const float4*)&ea[E*64 + j0];
            float o0 = r0.x + q0.x, o1 = r0.y + q0.y;
            float o2 = r1.x + q0.z, o3 = r1.y + q0.w;
            *(float4*)&out_eh[E*64 + j0] = make_float4(o0,o1,o2,o3);
            cs[0]+=o0; cs[1]+=o1; cs[2]+=o2; cs[3]+=o3;
            cq[0]+=o0*o0; cq[1]+=o1*o1; cq[2]+=o2*o2; cq[3]+=o3*o3;
        }
    }
    // BN sums reduce
    __syncthreads();
    float* red = sS;
    if (t < 128) red[t] = 0.f;
    __syncthreads();
    #pragma unroll
    for (int i = 0; i < 4; i++) {
        atomicAdd(&red[j0 + i], cs[i]);
        atomicAdd(&red[64 + j0 + i], cq[i]);
    }
    __syncthreads();
    if (t < 64) {
        atomicAdd(&g_sums[t],      (double)red[t]);
        atomicAdd(&g_sums[64 + t], (double)red[64 + t]);
    }
}

// ---------------- K: per-node attention accumulate (single pass) -----------
__global__ void __launch_bounds__(256) k_nattn() {
    int warp = threadIdx.x >> 5, lane = threadIdx.x & 31;
    int n = blockIdx.x*8 + warp;
    int c2 = lane*2;
    int deg = g_cnt[n];
    int base = g_base[n];
    if (deg == 0) {
        *(float2*)&g_oV[(size_t)n*64 + c2]     = make_float2(0.f, 0.f);
        *(float2*)&g_rowAcc[(size_t)n*64 + c2] = make_float2(0.f, 0.f);
        return;
    }
    int hh = lane >> 2;
    float dnacc = 0.f;
    float av0=0.f, av1=0.f, ar0=0.f, ar1=0.f;
    #pragma unroll 2
    for (int k = 0; k < deg; k++) {
        int idx = base + k;
        int eid = g_eord[idx];
        int src = g_esrc[idx];
        float ex = g_ex[(size_t)eid*8 + hh];
        dnacc += ex;
        float2 v = *(const float2*)&g_V[(size_t)src*64 + c2];
        float2 s = *(const float2*)&g_score[(size_t)eid*64 + c2];
        av0 = fmaf(v.x, ex, av0); av1 = fmaf(v.y, ex, av1);
        ar0 = fmaf(s.x, ex, ar0); ar1 = fmaf(s.y, ex, ar1);
    }
    float myr = 1.f / (dnacc + 1e-16f);
    *(float2*)&g_oV[(size_t)n*64 + c2]     = make_float2(av0*myr, av1*myr);
    *(float2*)&g_rowAcc[(size_t)n*64 + c2] = make_float2(ar0*myr, ar1*myr);
}

// ---------------- K: rowV einsum + deg + No gemm + residual + BN1 sums ----
__global__ void __launch_bounds__(256) k_node1(
    const float* __restrict__ x, const float* __restrict__ log_deg,
    const float* __restrict__ VeRow, const float* __restrict__ deg_coef,
    const float* __restrict__ No_w, const float* __restrict__ No_b)
{
    __shared__ __align__(16) float sNoT[64*64];
    __shared__ float sVe[512];
    __shared__ float sDC0[64], sDC1[64], sNob[64];
    __shared__ __align__(16) float sNH[16][64];
    __shared__ __align__(16) float sRA[16][64];
    int t = threadIdx.x;
    for (int i = t; i < 64*64; i += 256)
        sNoT[(i&63)*64 + (i>>6)] = No_w[i];
    for (int i = t; i < 512; i += 256) sVe[i] = VeRow[i];
    if (t < 64) { sDC0[t]=deg_coef[t*2]; sDC1[t]=deg_coef[t*2+1]; sNob[t]=No_b[t]; }
    __syncthreads();

    float cs0=0,cs1=0,cs2=0,cs3=0, cq0=0,cq1=0,cq2=0,cq3=0;
    int ngroups = NN/16;
    for (int g = blockIdx.x; g < ngroups; g += gridDim.x) {
        int n0 = g*16;
        for (int i = t; i < 16*64; i += 256)
            sRA[i>>6][i&63] = g_rowAcc[(size_t)(n0 + (i>>6))*64 + (i&63)];
        __syncthreads();
        int j = t & 63, h = j >> 3;
        #pragma unroll
        for (int qq = 0; qq < 4; qq++) {
            int le = (t >> 6) + qq*4;
            int n = n0 + le;
            float rv = 0.f;
            #pragma unroll
            for (int d = 0; d < 8; d++)
                rv = fmaf(sRA[le][h*8+d], sVe[d*64 + j], rv);
            float nh0 = g_oV[(size_t)n*64 + j] + rv;
            float ld = log_deg[n];
            sNH[le][j] = nh0 * (sDC0[j] + ld*sDC1[j]);
        }
        __syncthreads();
        {
            int j4 = (t & 15) * 4;
            int le = t >> 4;
            int n = n0 + le;
            float4 acc = make_float4(sNob[j4], sNob[j4+1], sNob[j4+2], sNob[j4+3]);
            #pragma unroll 8
            for (int d = 0; d < 64; d++) {
                float a = sNH[le][d];
                float4 w = *(const float4*)&sNoT[d*64 + j4];
                acc.x = fmaf(a,w.x,acc.x); acc.y = fmaf(a,w.y,acc.y);
                acc.z = fmaf(a,w.z,acc.z); acc.w = fmaf(a,w.w,acc.w);
            }
            float4 xr = *(const float4*)&x[(size_t)n*64 + j4];
            acc.x += xr.x; acc.y += xr.y; acc.z += xr.z; acc.w += xr.w;
            *(float4*)&g_nh1[(size_t)n*64 + j4] = acc;
            cs0 += acc.x; cs1 += acc.y; cs2 += acc.z; cs3 += acc.w;
            cq0 += acc.x*acc.x; cq1 += acc.y*acc.y; cq2 += acc.z*acc.z; cq3 += acc.w*acc.w;
        }
        __syncthreads();
    }
    float* red = &sRA[0][0];
    if (t < 128) red[t] = 0.f;
    __syncthreads();
    int j4 = (t & 15) * 4;
    atomicAdd(&red[j4+0], cs0); atomicAdd(&red[j4+1], cs1);
    atomicAdd(&red[j4+2], cs2); atomicAdd(&red[j4+3], cs3);
    atomicAdd(&red[64+j4+0], cq0); atomicAdd(&red[64+j4+1], cq1);
    atomicAdd(&red[64+j4+2], cq2); atomicAdd(&red[64+j4+3], cq3);
    __syncthreads();
    if (t < 64) {
        atomicAdd(&g_sums[128+t], (double)red[t]);
        atomicAdd(&g_sums[192+t], (double)red[64+t]);
    }
}

// ---------------- K: BN params (edge, node1) ----------------
__global__ void k_bnp1(const float* __restrict__ g1e, const float* __restrict__ b1e,
                       const float* __restrict__ g1n, const float* __restrict__ b1n) {
    int t = threadIdx.x;
    if (t < 64) {
        double mu = g_sums[t] / (double)NEE;
        double var = g_sums[64+t] / (double)NEE - mu*mu;
        float sc = (float)(1.0/sqrt(var + 1e-5)) * g1e[t];
        g_bnp[t] = sc; g_bnp[64+t] = b1e[t] - (float)mu*sc;
    } else {
        int j = t - 64;
        double mu = g_sums[128+j] / (double)NN;
        double var = g_sums[192+j] / (double)NN - mu*mu;
        float sc = (float)(1.0/sqrt(var + 1e-5)) * g1n[j];
        g_bnp[128+j] = sc; g_bnp[192+j] = b1n[j] - (float)mu*sc;
    }
}

// ---------------- K: BN1 apply + MLP + residual + BN2 sums ----------------
__global__ void __launch_bounds__(256) k_mlp(
    const float* __restrict__ W1, const float* __restrict__ b1f,
    const float* __restrict__ W2, const float* __restrict__ b2f)
{
    extern __shared__ float dynm[];
    float* sW1 = dynm;           // [d][k] 64*128
    float* sW2 = dynm + 8192;    // [k][j] 128*64
    float* sHf = dynm + 16384;   // [le][k] 16*128
    float* sBv = dynm + 18432;   // [le][j] 16*64
    __shared__ float sb1[128];
    __shared__ float sb2[64], sScale[64], sShift[64];
    int t = threadIdx.x;
    if (t < 128) sb1[t] = b1f[t];
    if (t < 64) { sb2[t]=b2f[t]; sScale[t]=g_bnp[128+t]; sShift[t]=g_bnp[192+t]; }
    for (int i = t; i < 128*64; i += 256) {
        int k = i >> 6, d = i & 63;
        sW1[d*128 + k] = W1[i];
        int j = i >> 7, k2 = i & 127;
        sW2[k2*64 + j] = W2[i];
    }

    float cs0=0,cs1=0,cs2=0,cs3=0, cq0=0,cq1=0,cq2=0,cq3=0;
    int ngroups = NN/16;
    for (int g = blockIdx.x; g < ngroups; g += gridDim.x) {
        int n0 = g*16;
        __syncthreads();
        for (int i = t; i < 16*64; i += 256) {
            int le = i >> 6, j = i & 63;
            sBv[le*64 + j] = g_nh1[(size_t)(n0+le)*64 + j]*sScale[j] + sShift[j];
        }
        __syncthreads();
        {
            int k4 = (t & 31) * 4;
            int le0 = t >> 5;
            float4 acc0 = make_float4(sb1[k4], sb1[k4+1], sb1[k4+2], sb1[k4+3]);
            float4 acc1 = acc0;
            #pragma unroll 8
            for (int d = 0; d < 64; d++) {
                float4 w = *(const float4*)&sW1[d*128 + k4];
                float a0 = sBv[le0*64 + d], a1 = sBv[(le0+8)*64 + d];
                acc0.x = fmaf(a0,w.x,acc0.x); acc0.y = fmaf(a0,w.y,acc0.y);
                acc0.z = fmaf(a0,w.z,acc0.z); acc0.w = fmaf(a0,w.w,acc0.w);
                acc1.x = fmaf(a1,w.x,acc1.x); acc1.y = fmaf(a1,w.y,acc1.y);
                acc1.z = fmaf(a1,w.z,acc1.z); acc1.w = fmaf(a1,w.w,acc1.w);
            }
            acc0.x=fmaxf(acc0.x,0.f); acc0.y=fmaxf(acc0.y,0.f); acc0.z=fmaxf(acc0.z,0.f); acc0.w=fmaxf(acc0.w,0.f);
            acc1.x=fmaxf(acc1.x,0.f); acc1.y=fmaxf(acc1.y,0.f); acc1.z=fmaxf(acc1.z,0.f); acc1.w=fmaxf(acc1.w,0.f);
            *(float4*)&sHf[le0*128 + k4]     = acc0;
            *(float4*)&sHf[(le0+8)*128 + k4] = acc1;
        }
        __syncthreads();
        {
            int j4 = (t & 15) * 4;
            int le = t >> 4;
            int n = n0 + le;
            float4 acc = make_float4(sb2[j4], sb2[j4+1], sb2[j4+2], sb2[j4+3]);
            #pragma unroll 8
            for (int k = 0; k < 128; k++) {
                float a = sHf[le*128 + k];
                float4 w = *(const float4*)&sW2[k*64 + j4];
                acc.x = fmaf(a,w.x,acc.x); acc.y = fmaf(a,w.y,acc.y);
                acc.z = fmaf(a,w.z,acc.z); acc.w = fmaf(a,w.w,acc.w);
            }
            acc.x += sBv[le*64 + j4+0]; acc.y += sBv[le*64 + j4+1];
            acc.z += sBv[le*64 + j4+2]; acc.w += sBv[le*64 + j4+3];
            *(float4*)&g_nh3[(size_t)n*64 + j4] = acc;
            cs0 += acc.x; cs1 += acc.y; cs2 += acc.z; cs3 += acc.w;
            cq0 += acc.x*acc.x; cq1 += acc.y*acc.y; cq2 += acc.z*acc.z; cq3 += acc.w*acc.w;
        }
    }
    __syncthreads();
    float* red = sHf;
    if (t < 128) red[t] = 0.f;
    __syncthreads();
    int j4 = (t & 15) * 4;
    atomicAdd(&red[j4+0], cs0); atomicAdd(&red[j4+1], cs1);
    atomicAdd(&red[j4+2], cs2); atomicAdd(&red[j4+3], cs3);
    atomicAdd(&red[64+j4+0], cq0); atomicAdd(&red[64+j4+1], cq1);
    atomicAdd(&red[64+j4+2], cq2); atomicAdd(&red[64+j4+3], cq3);
    __syncthreads();
    if (t < 64) {
        atomicAdd(&g_sums[256+t], (double)red[t]);
        atomicAdd(&g_sums[320+t], (double)red[64+t]);
    }
}

// ---------------- K: BN2 params ----------------
__global__ void k_bnp2(const float* __restrict__ g2, const float* __restrict__ beta2) {
    int t = threadIdx.x;
    double mu = g_sums[256+t] / (double)NN;
    double var = g_sums[320+t] / (double)NN - mu*mu;
    float sc = (float)(1.0/sqrt(var + 1e-5)) * g2[t];
    g_bnp[256+t] = sc; g_bnp[320+t] = beta2[t] - (float)mu*sc;
}

// ---------------- K: apply BN2 (nodes) + edge BN (in place) ----------------
__global__ void k_finish(float* __restrict__ out) {
    const int NODE4 = NN*16;
    const int TOT4 = NODE4 + NEE*16;
    int q = blockIdx.x*blockDim.x + threadIdx.x;
    if (q >= TOT4) return;
    int j = (q*4) & 63;
    if (q < NODE4) {
        float4 v = *(const float4*)&g_nh3[(size_t)q*4];
        float4 sc = *(const float4*)&g_bnp[256+j];
        float4 sh = *(const float4*)&g_bnp[320+j];
        float4 r;
        r.x = v.x*sc.x + sh.x; r.y = v.y*sc.y + sh.y;
        r.z = v.z*sc.z + sh.z; r.w = v.w*sc.w + sh.w;
        ((float4*)out)[q] = r;
    } else {
        float4 v = ((const float4*)out)[q];
        float4 sc = *(const float4*)&g_bnp[j];
        float4 sh = *(const float4*)&g_bnp[64+j];
        float4 r;
        r.x = v.x*sc.x + sh.x; r.y = v.y*sc.y + sh.y;
        r.z = v.z*sc.z + sh.z; r.w = v.w*sc.w + sh.w;
        ((float4*)out)[q] = r;
    }
}

// ---------------- launch ----------------
extern "C" void kernel_launch(void* const* d_in, const int* in_sizes, int n_in,
                              void* d_out, int out_size) {
    const float* x        = (const float*)d_in[0];
    const float* ea       = (const float*)d_in[1];
    const float* log_deg  = (const float*)d_in[2];
    const int*   eidx     = (const int*)d_in[3];
    const float* Wq = (const float*)d_in[4];  const float* bq = (const float*)d_in[5];
    const float* Wk = (const float*)d_in[6];  const float* bk = (const float*)d_in[7];
    const float* Wv = (const float*)d_in[8];  const float* bv = (const float*)d_in[9];
    const float* We = (const float*)d_in[10]; const float* be = (const float*)d_in[11];
    const float* Aw = (const float*)d_in[12]; const float* VeRow = (const float*)d_in[13];
    const float* deg_coef = (const float*)d_in[14];
    const float* No_w = (const float*)d_in[15]; const float* No_b = (const float*)d_in[16];
    const float* Eo_w = (const float*)d_in[17]; const float* Eo_b = (const float*)d_in[18];
    const float* W1 = (const float*)d_in[19]; const float* b1f = (const float*)d_in[20];
    const float* W2 = (const float*)d_in[21]; const float* b2f = (const float*)d_in[22];
    const float* g1n = (const float*)d_in[23]; const float* b1n = (const float*)d_in[24];
    const float* g1e = (const float*)d_in[25]; const float* b1e = (const float*)d_in[26];
    const float* g2  = (const float*)d_in[27]; const float* beta2 = (const float*)d_in[28];

    float* out = (float*)d_out;
    float* out_eh = out + (size_t)NN*64;

    const int QKV_SMEM   = (12288 + 8192) * 4;  // 80 KB
    const int EDGE1_SMEM = 16384 * 4;           // 64 KB
    const int EDGE2_SMEM = 12288 * 4;           // 48 KB -> 3 CTAs/SM
    const int MLP_SMEM   = 19456 * 4;           // 76 KB
    cudaFuncSetAttribute(k_qkv,   cudaFuncAttributeMaxDynamicSharedMemorySize, QKV_SMEM);
    cudaFuncSetAttribute(k_edge1, cudaFuncAttributeMaxDynamicSharedMemorySize, EDGE1_SMEM);
    cudaFuncSetAttribute(k_edge2, cudaFuncAttributeMaxDynamicSharedMemorySize, EDGE2_SMEM);
    cudaFuncSetAttribute(k_mlp,   cudaFuncAttributeMaxDynamicSharedMemorySize, MLP_SMEM);

    // order: k_edge1 at launch index 3 so ncu's fixed capture lands on it
    k_qkv   <<<391, 256, QKV_SMEM>>>(x, Wq, bq, Wk, bk, Wv, bv);     // 0
    k_init  <<<196, 256>>>();                                        // 1
    k_hist  <<<3125, 256>>>(eidx);                                   // 2
    k_edge1 <<<2960, 256, EDGE1_SMEM>>>(ea, eidx, We, be, Aw);       // 3
    k_edge2 <<<4440, 256, EDGE2_SMEM>>>(ea, Eo_w, Eo_b, out_eh);     // 4
    k_scan1 <<<196, 256>>>();                                        // 5
    k_scan2 <<<1, 256>>>();                                          // 6
    k_scan3 <<<196, 256>>>();                                        // 7
    k_sids  <<<3125, 256>>>(eidx);                                   // 8
    k_nattn <<<6250, 256>>>();                                       // 9
    k_node1 <<<592, 256>>>(x, log_deg, VeRow, deg_coef, No_w, No_b); // 10
    k_bnp1  <<<1, 128>>>(g1e, b1e, g1n, b1n);                        // 11
    k_mlp   <<<592, 256, MLP_SMEM>>>(W1, b1f, W2, b2f);              // 12
    k_bnp2  <<<1, 64>>>(g2, beta2);                                  // 13
    k_finish<<<53125, 256>>>(out);                                   // 14
}